// round 1
// baseline (speedup 1.0000x reference)
#include <cuda_runtime.h>
#include <cuda_bf16.h>
#include <math.h>

// Problem constants
#define BATCH 16
#define SEQ   512
#define DMODEL 2048
#define NHEADS 16
#define NGROUPS 4
#define HEADD 128
#define PPG   (NHEADS / NGROUPS)   // 4
#define KVD   (NGROUPS * HEADD)    // 512
#define MROWS (BATCH * SEQ)        // 8192

#define INV_SQRT_HD 0.08838834764831845f
#define LN10000 9.210340371976184f

// ---------------------------------------------------------------------------
// Scratch buffers (static __device__, allocation-free)
// ---------------------------------------------------------------------------
__device__ float g_q[(size_t)MROWS * DMODEL];     // 64 MB
__device__ float g_k[(size_t)MROWS * KVD];        // 16 MB
__device__ float g_v[(size_t)MROWS * KVD];        // 16 MB
__device__ float g_attn[(size_t)MROWS * DMODEL];  // 64 MB

// ---------------------------------------------------------------------------
// Kernel 1: C[M,N] = A[M,K] @ B[K,N] + bias[N]    (fp32, 128x128x8 tiling)
// Assumes M%128==0, N%128==0, K%8==0, K%4==0 (true for all our shapes)
// ---------------------------------------------------------------------------
__global__ __launch_bounds__(256, 2)
void sgemm_bias_kernel(const float* __restrict__ A, const float* __restrict__ B,
                       const float* __restrict__ bias, float* __restrict__ C,
                       int M, int N, int K) {
    __shared__ float As[8][128];   // As[k][m]  (transposed)
    __shared__ float Bs[8][128];   // Bs[k][n]

    const int tid = threadIdx.x;
    const int tx = tid & 15;        // 0..15  (n dim)
    const int ty = tid >> 4;        // 0..15  (m dim)
    const int m0 = blockIdx.y * 128;
    const int n0 = blockIdx.x * 128;

    // A load mapping: tile [128 m][8 k]; each thread 1 float4 along k
    const int a_m = tid >> 1;            // 0..127
    const int a_k = (tid & 1) * 4;       // 0 or 4
    // B load mapping: tile [8 k][128 n]; each thread 1 float4 along n
    const int b_k = tid >> 5;            // 0..7
    const int b_n = (tid & 31) * 4;      // 0..124

    float acc[8][8];
    #pragma unroll
    for (int i = 0; i < 8; i++)
        #pragma unroll
        for (int j = 0; j < 8; j++) acc[i][j] = 0.0f;

    for (int kt = 0; kt < K; kt += 8) {
        // load A tile (transpose into As[k][m])
        float4 av = *reinterpret_cast<const float4*>(&A[(size_t)(m0 + a_m) * K + kt + a_k]);
        As[a_k + 0][a_m] = av.x;
        As[a_k + 1][a_m] = av.y;
        As[a_k + 2][a_m] = av.z;
        As[a_k + 3][a_m] = av.w;
        // load B tile
        *reinterpret_cast<float4*>(&Bs[b_k][b_n]) =
            *reinterpret_cast<const float4*>(&B[(size_t)(kt + b_k) * N + n0 + b_n]);
        __syncthreads();

        #pragma unroll
        for (int kk = 0; kk < 8; kk++) {
            float4 a0 = *reinterpret_cast<float4*>(&As[kk][ty * 8]);
            float4 a1 = *reinterpret_cast<float4*>(&As[kk][ty * 8 + 4]);
            float4 b0 = *reinterpret_cast<float4*>(&Bs[kk][tx * 8]);
            float4 b1 = *reinterpret_cast<float4*>(&Bs[kk][tx * 8 + 4]);
            float ar[8] = {a0.x, a0.y, a0.z, a0.w, a1.x, a1.y, a1.z, a1.w};
            float br[8] = {b0.x, b0.y, b0.z, b0.w, b1.x, b1.y, b1.z, b1.w};
            #pragma unroll
            for (int i = 0; i < 8; i++)
                #pragma unroll
                for (int j = 0; j < 8; j++)
                    acc[i][j] = fmaf(ar[i], br[j], acc[i][j]);
        }
        __syncthreads();
    }

    // epilogue with bias
    #pragma unroll
    for (int i = 0; i < 8; i++) {
        int row = m0 + ty * 8 + i;
        int col = n0 + tx * 8;
        float4 bb0 = *reinterpret_cast<const float4*>(&bias[col]);
        float4 bb1 = *reinterpret_cast<const float4*>(&bias[col + 4]);
        float4 c0 = make_float4(acc[i][0] + bb0.x, acc[i][1] + bb0.y,
                                acc[i][2] + bb0.z, acc[i][3] + bb0.w);
        float4 c1 = make_float4(acc[i][4] + bb1.x, acc[i][5] + bb1.y,
                                acc[i][6] + bb1.z, acc[i][7] + bb1.w);
        *reinterpret_cast<float4*>(&C[(size_t)row * N + col]) = c0;
        *reinterpret_cast<float4*>(&C[(size_t)row * N + col + 4]) = c1;
    }
}

// ---------------------------------------------------------------------------
// Kernel 2: fused RMSNorm + RoPE (in-place) per (b,s,head) 128-vector
// grid = BATCH*SEQ*nheads blocks, 128 threads
// ---------------------------------------------------------------------------
__global__ __launch_bounds__(128)
void rmsnorm_rope_kernel(float* __restrict__ buf, const float* __restrict__ scale,
                         int nheads, float post_scale) {
    __shared__ float sh[128];
    __shared__ float red[4];
    const int tid = threadIdx.x;
    float* ptr = buf + (size_t)blockIdx.x * HEADD;
    const int s = (blockIdx.x / nheads) % SEQ;

    float v = ptr[tid];
    float sq = v * v;
    #pragma unroll
    for (int o = 16; o > 0; o >>= 1) sq += __shfl_xor_sync(0xffffffffu, sq, o);
    if ((tid & 31) == 0) red[tid >> 5] = sq;
    __syncthreads();
    float total = red[0] + red[1] + red[2] + red[3];
    float r = rsqrtf(total * (1.0f / 128.0f) + 1e-6f);
    sh[tid] = v * r * scale[tid];
    __syncthreads();

    const int ip = tid >> 1;
    float x1 = sh[ip * 2];
    float x2 = sh[ip * 2 + 1];
    // inv_freq = 10000^(-ip/64) computed via expf for precision
    float inv_freq = expf((float)ip * (-LN10000 / 64.0f));
    float ang = (float)s * inv_freq;
    float sn, cs;
    sincosf(ang, &sn, &cs);
    float out = (tid & 1) ? fmaf(x1, sn, x2 * cs) : fmaf(x1, cs, -x2 * sn);
    ptr[tid] = out * post_scale;
}

// ---------------------------------------------------------------------------
// Kernel 3: causal attention for one (b,h,q-tile=64 rows)
// Full score rows (<=512) materialized in smem; exact 2-pass softmax.
// grid = (SEQ/64, BATCH*NHEADS), block = 256
// dyn smem layout (floats):
//   scores : 64 * 516
//   Qs     : 128 * 68      (Qs[k][r], transposed)
//   KVs    : 128 * 68      (phase1: Ks[k][c] transposed; phase3: Vs[k][c] stride 132)
// ---------------------------------------------------------------------------
#define SC_STRIDE 516
#define QT_STRIDE 68
#define V_STRIDE  132
#define SMEM_FLOATS (64 * SC_STRIDE + 128 * QT_STRIDE + 128 * QT_STRIDE)

__global__ __launch_bounds__(256)
void attention_kernel(const float* __restrict__ Q, const float* __restrict__ K,
                      const float* __restrict__ V, float* __restrict__ O) {
    extern __shared__ float smem[];
    float* scores = smem;                       // 64 x 516
    float* Qs = scores + 64 * SC_STRIDE;        // 128 x 68
    float* KVs = Qs + 128 * QT_STRIDE;          // 128 x 68 (or 64 x 132)

    const int tid = threadIdx.x;
    const int tx = tid & 15;
    const int ty = tid >> 4;
    const int qt = blockIdx.x;                  // 0..7
    const int bh = blockIdx.y;                  // 0..255
    const int b = bh / NHEADS;
    const int h = bh % NHEADS;
    const int g = h / PPG;

    const float* Qbase = Q + (size_t)b * SEQ * DMODEL + (size_t)h * HEADD;
    const float* Kbase = K + (size_t)b * SEQ * KVD + (size_t)g * HEADD;
    const float* Vbase = V + (size_t)b * SEQ * KVD + (size_t)g * HEADD;

    // load Q tile transposed: Qs[k][r]
    for (int i = tid; i < 64 * 128; i += 256) {
        int r = i >> 7, k = i & 127;
        Qs[k * QT_STRIDE + r] = Qbase[(size_t)(qt * 64 + r) * DMODEL + k];
    }

    // ---------------- phase 1: scores ----------------
    for (int kt = 0; kt <= qt; kt++) {
        __syncthreads();
        for (int i = tid; i < 64 * 128; i += 256) {
            int r = i >> 7, k = i & 127;
            KVs[k * QT_STRIDE + r] = Kbase[(size_t)(kt * 64 + r) * KVD + k];
        }
        __syncthreads();

        float acc[4][4];
        #pragma unroll
        for (int i = 0; i < 4; i++)
            #pragma unroll
            for (int j = 0; j < 4; j++) acc[i][j] = 0.0f;

        #pragma unroll 4
        for (int kk = 0; kk < 128; kk++) {
            float4 a = *reinterpret_cast<float4*>(&Qs[kk * QT_STRIDE + ty * 4]);
            float4 bb = *reinterpret_cast<float4*>(&KVs[kk * QT_STRIDE + tx * 4]);
            float ar[4] = {a.x, a.y, a.z, a.w};
            float br[4] = {bb.x, bb.y, bb.z, bb.w};
            #pragma unroll
            for (int i = 0; i < 4; i++)
                #pragma unroll
                for (int j = 0; j < 4; j++)
                    acc[i][j] = fmaf(ar[i], br[j], acc[i][j]);
        }

        #pragma unroll
        for (int i = 0; i < 4; i++) {
            int r = ty * 4 + i;
            int grow = qt * 64 + r;
            #pragma unroll
            for (int j = 0; j < 4; j++) {
                int c = tx * 4 + j;
                int gcol = kt * 64 + c;
                float val = (gcol <= grow) ? acc[i][j] * INV_SQRT_HD : -1e30f;
                scores[r * SC_STRIDE + kt * 64 + c] = val;
            }
        }
    }
    __syncthreads();

    // ---------------- phase 2: softmax ----------------
    const int ncols = (qt + 1) * 64;
    const int warp = tid >> 5;
    const int lane = tid & 31;
    for (int r = warp; r < 64; r += 8) {
        float* row = &scores[r * SC_STRIDE];
        float m = -1e30f;
        for (int c = lane; c < ncols; c += 32) m = fmaxf(m, row[c]);
        #pragma unroll
        for (int o = 16; o > 0; o >>= 1) m = fmaxf(m, __shfl_xor_sync(0xffffffffu, m, o));
        float sum = 0.0f;
        for (int c = lane; c < ncols; c += 32) {
            float e = __expf(row[c] - m);
            row[c] = e;
            sum += e;
        }
        #pragma unroll
        for (int o = 16; o > 0; o >>= 1) sum += __shfl_xor_sync(0xffffffffu, sum, o);
        float inv = 1.0f / sum;
        for (int c = lane; c < ncols; c += 32) row[c] *= inv;
    }
    __syncthreads();

    // ---------------- phase 3: O = P @ V ----------------
    float oacc[4][8];
    #pragma unroll
    for (int i = 0; i < 4; i++)
        #pragma unroll
        for (int j = 0; j < 8; j++) oacc[i][j] = 0.0f;

    for (int kt = 0; kt <= qt; kt++) {
        __syncthreads();
        for (int i = tid; i < 64 * 128; i += 256) {
            int r = i >> 7, c = i & 127;
            KVs[r * V_STRIDE + c] = Vbase[(size_t)(kt * 64 + r) * KVD + c];
        }
        __syncthreads();

        #pragma unroll 2
        for (int kk = 0; kk < 64; kk++) {
            float p[4];
            #pragma unroll
            for (int i = 0; i < 4; i++)
                p[i] = scores[(ty * 4 + i) * SC_STRIDE + kt * 64 + kk];
            float4 v0 = *reinterpret_cast<float4*>(&KVs[kk * V_STRIDE + tx * 8]);
            float4 v1 = *reinterpret_cast<float4*>(&KVs[kk * V_STRIDE + tx * 8 + 4]);
            float vr[8] = {v0.x, v0.y, v0.z, v0.w, v1.x, v1.y, v1.z, v1.w};
            #pragma unroll
            for (int i = 0; i < 4; i++)
                #pragma unroll
                for (int j = 0; j < 8; j++)
                    oacc[i][j] = fmaf(p[i], vr[j], oacc[i][j]);
        }
    }

    // write O to attn buffer in (b,s,d) layout, d = h*128 + c
    #pragma unroll
    for (int i = 0; i < 4; i++) {
        int srow = qt * 64 + ty * 4 + i;
        float* dst = &g_attn[((size_t)b * SEQ + srow) * DMODEL + h * HEADD + tx * 8];
        float4 c0 = make_float4(oacc[i][0], oacc[i][1], oacc[i][2], oacc[i][3]);
        float4 c1 = make_float4(oacc[i][4], oacc[i][5], oacc[i][6], oacc[i][7]);
        *reinterpret_cast<float4*>(dst) = c0;
        *reinterpret_cast<float4*>(dst + 4) = c1;
    }
}

// ---------------------------------------------------------------------------
// Launch
// ---------------------------------------------------------------------------
extern "C" void kernel_launch(void* const* d_in, const int* in_sizes, int n_in,
                              void* d_out, int out_size) {
    const float* x  = (const float*)d_in[0];
    const float* Wq = (const float*)d_in[1];
    const float* bq = (const float*)d_in[2];
    const float* Wk = (const float*)d_in[3];
    const float* bk = (const float*)d_in[4];
    const float* Wv = (const float*)d_in[5];
    const float* bv = (const float*)d_in[6];
    const float* Wo = (const float*)d_in[7];
    const float* bo = (const float*)d_in[8];
    const float* qns = (const float*)d_in[9];
    const float* kns = (const float*)d_in[10];
    float* out = (float*)d_out;

    float *qb, *kb, *vb, *ab;
    cudaGetSymbolAddress((void**)&qb, g_q);
    cudaGetSymbolAddress((void**)&kb, g_k);
    cudaGetSymbolAddress((void**)&vb, g_v);
    cudaGetSymbolAddress((void**)&ab, g_attn);

    // QKV projections
    sgemm_bias_kernel<<<dim3(DMODEL / 128, MROWS / 128), 256>>>(x, Wq, bq, qb, MROWS, DMODEL, DMODEL);
    sgemm_bias_kernel<<<dim3(KVD / 128,    MROWS / 128), 256>>>(x, Wk, bk, kb, MROWS, KVD, DMODEL);
    sgemm_bias_kernel<<<dim3(KVD / 128,    MROWS / 128), 256>>>(x, Wv, bv, vb, MROWS, KVD, DMODEL);

    // RMSNorm + RoPE (Q also gets the first inv_sqrt_hd factor)
    rmsnorm_rope_kernel<<<BATCH * SEQ * NHEADS, 128>>>(qb, qns, NHEADS, INV_SQRT_HD);
    rmsnorm_rope_kernel<<<BATCH * SEQ * NGROUPS, 128>>>(kb, kns, NGROUPS, 1.0f);

    // Attention
    static const size_t smem_bytes = (size_t)SMEM_FLOATS * sizeof(float);
    cudaFuncSetAttribute(attention_kernel, cudaFuncAttributeMaxDynamicSharedMemorySize,
                         (int)smem_bytes);
    attention_kernel<<<dim3(SEQ / 64, BATCH * NHEADS), 256, smem_bytes>>>(qb, kb, vb, ab);

    // Output projection
    sgemm_bias_kernel<<<dim3(DMODEL / 128, MROWS / 128), 256>>>(ab, Wo, bo, out, MROWS, DMODEL, DMODEL);
}

// round 2
// speedup vs baseline: 1.3879x; 1.3879x over previous
#include <cuda_runtime.h>
#include <cuda_bf16.h>
#include <math.h>

// Problem constants
#define BATCH 16
#define SEQ   512
#define DMODEL 2048
#define NHEADS 16
#define NGROUPS 4
#define HEADD 128
#define PPG   (NHEADS / NGROUPS)   // 4
#define KVD   (NGROUPS * HEADD)    // 512
#define MROWS (BATCH * SEQ)        // 8192

#define INV_SQRT_HD 0.08838834764831845f
#define LN10000 9.210340371976184f

// ---------------------------------------------------------------------------
// Scratch buffers (static __device__, allocation-free)
// ---------------------------------------------------------------------------
__device__ float g_q[(size_t)MROWS * DMODEL];     // 64 MB
__device__ float g_k[(size_t)MROWS * KVD];        // 16 MB
__device__ float g_v[(size_t)MROWS * KVD];        // 16 MB
__device__ float g_attn[(size_t)MROWS * DMODEL];  // 64 MB

// ---------------------------------------------------------------------------
// TF32 helpers
// ---------------------------------------------------------------------------
__device__ __forceinline__ unsigned f2tf32(float x) {
    unsigned r;
    asm("cvt.rna.tf32.f32 %0, %1;" : "=r"(r) : "f"(x));
    return r;
}

__device__ __forceinline__ void mma_tf32(float c[4], const unsigned a[4], const unsigned b[2]) {
    asm volatile(
        "mma.sync.aligned.m16n8k8.row.col.f32.tf32.tf32.f32 "
        "{%0,%1,%2,%3}, {%4,%5,%6,%7}, {%8,%9}, {%0,%1,%2,%3};"
        : "+f"(c[0]), "+f"(c[1]), "+f"(c[2]), "+f"(c[3])
        : "r"(a[0]), "r"(a[1]), "r"(a[2]), "r"(a[3]), "r"(b[0]), "r"(b[1]));
}

// ---------------------------------------------------------------------------
// Kernel 1: C[M,N] = A[M,K] @ B[K,N] + bias[N]   (TF32 tensor cores)
// Block tile 128x128, K-step 32. 256 threads = 8 warps (2 x 4),
// each warp computes 64x32 via 4x4 m16n8k8 mma tiles.
// Assumes M%128==0, N%128==0, K%32==0.
// ---------------------------------------------------------------------------
#define AS_STRIDE 36    // bank = (4r + c) % 32 -> conflict-free frag loads
#define BS_STRIDE 136   // bank = (8k + n) % 32 -> conflict-free frag loads

__global__ __launch_bounds__(256, 2)
void tf32_gemm_bias(const float* __restrict__ A, const float* __restrict__ B,
                    const float* __restrict__ bias, float* __restrict__ C,
                    int M, int N, int K) {
    __shared__ unsigned As[128 * AS_STRIDE];  // A tile [m][k] 128x32 (padded)
    __shared__ unsigned Bs[32 * BS_STRIDE];   // B tile [k][n] 32x128 (padded)

    const int tid = threadIdx.x;
    const int lane = tid & 31;
    const int wid = tid >> 5;
    const int warpRow = (wid >> 2) * 64;   // 0 or 64
    const int warpCol = (wid & 3) * 32;    // 0,32,64,96
    const int m0 = blockIdx.y * 128;
    const int n0 = blockIdx.x * 128;

    float acc[4][4][4];   // [rowTile][colTile][creg]
    #pragma unroll
    for (int i = 0; i < 4; i++)
        #pragma unroll
        for (int j = 0; j < 4; j++)
            #pragma unroll
            for (int r = 0; r < 4; r++) acc[i][j][r] = 0.0f;

    const int lr = lane >> 2;   // 0..7
    const int lc = lane & 3;    // 0..3

    for (int kt = 0; kt < K; kt += 32) {
        // --- load A tile: 128x32 floats = 1024 float4 slots ---
        #pragma unroll
        for (int i = 0; i < 4; i++) {
            int s = tid + i * 256;
            int r = s >> 3;
            int c4 = (s & 7) * 4;
            float4 v = *reinterpret_cast<const float4*>(&A[(size_t)(m0 + r) * K + kt + c4]);
            As[r * AS_STRIDE + c4 + 0] = f2tf32(v.x);
            As[r * AS_STRIDE + c4 + 1] = f2tf32(v.y);
            As[r * AS_STRIDE + c4 + 2] = f2tf32(v.z);
            As[r * AS_STRIDE + c4 + 3] = f2tf32(v.w);
        }
        // --- load B tile: 32x128 floats = 1024 float4 slots ---
        #pragma unroll
        for (int i = 0; i < 4; i++) {
            int s = tid + i * 256;
            int r = s >> 5;
            int c4 = (s & 31) * 4;
            float4 v = *reinterpret_cast<const float4*>(&B[(size_t)(kt + r) * N + n0 + c4]);
            Bs[r * BS_STRIDE + c4 + 0] = f2tf32(v.x);
            Bs[r * BS_STRIDE + c4 + 1] = f2tf32(v.y);
            Bs[r * BS_STRIDE + c4 + 2] = f2tf32(v.z);
            Bs[r * BS_STRIDE + c4 + 3] = f2tf32(v.w);
        }
        __syncthreads();

        #pragma unroll
        for (int ks = 0; ks < 4; ks++) {
            const int k0 = ks * 8;
            unsigned af[4][4];
            unsigned bf[4][2];
            #pragma unroll
            for (int it = 0; it < 4; it++) {
                int r = warpRow + it * 16 + lr;
                int c = k0 + lc;
                af[it][0] = As[r * AS_STRIDE + c];
                af[it][1] = As[(r + 8) * AS_STRIDE + c];
                af[it][2] = As[r * AS_STRIDE + c + 4];
                af[it][3] = As[(r + 8) * AS_STRIDE + c + 4];
            }
            #pragma unroll
            for (int jt = 0; jt < 4; jt++) {
                int kk = k0 + lc;
                int nn = warpCol + jt * 8 + lr;
                bf[jt][0] = Bs[kk * BS_STRIDE + nn];
                bf[jt][1] = Bs[(kk + 4) * BS_STRIDE + nn];
            }
            #pragma unroll
            for (int it = 0; it < 4; it++)
                #pragma unroll
                for (int jt = 0; jt < 4; jt++)
                    mma_tf32(acc[it][jt], af[it], bf[jt]);
        }
        __syncthreads();
    }

    // --- epilogue with bias ---
    #pragma unroll
    for (int it = 0; it < 4; it++) {
        #pragma unroll
        for (int jt = 0; jt < 4; jt++) {
            int row = m0 + warpRow + it * 16 + lr;
            int col = n0 + warpCol + jt * 8 + 2 * lc;
            float b0 = bias[col];
            float b1 = bias[col + 1];
            float2 v0 = make_float2(acc[it][jt][0] + b0, acc[it][jt][1] + b1);
            float2 v1 = make_float2(acc[it][jt][2] + b0, acc[it][jt][3] + b1);
            *reinterpret_cast<float2*>(&C[(size_t)row * N + col]) = v0;
            *reinterpret_cast<float2*>(&C[(size_t)(row + 8) * N + col]) = v1;
        }
    }
}

// ---------------------------------------------------------------------------
// Kernel 2: fused RMSNorm + RoPE (in-place) per (b,s,head) 128-vector
// ---------------------------------------------------------------------------
__global__ __launch_bounds__(128)
void rmsnorm_rope_kernel(float* __restrict__ buf, const float* __restrict__ scale,
                         int nheads, float post_scale) {
    __shared__ float sh[128];
    __shared__ float red[4];
    const int tid = threadIdx.x;
    float* ptr = buf + (size_t)blockIdx.x * HEADD;
    const int s = (blockIdx.x / nheads) % SEQ;

    float v = ptr[tid];
    float sq = v * v;
    #pragma unroll
    for (int o = 16; o > 0; o >>= 1) sq += __shfl_xor_sync(0xffffffffu, sq, o);
    if ((tid & 31) == 0) red[tid >> 5] = sq;
    __syncthreads();
    float total = red[0] + red[1] + red[2] + red[3];
    float r = rsqrtf(total * (1.0f / 128.0f) + 1e-6f);
    sh[tid] = v * r * scale[tid];
    __syncthreads();

    const int ip = tid >> 1;
    float x1 = sh[ip * 2];
    float x2 = sh[ip * 2 + 1];
    float inv_freq = expf((float)ip * (-LN10000 / 64.0f));
    float ang = (float)s * inv_freq;
    float sn, cs;
    sincosf(ang, &sn, &cs);
    float out = (tid & 1) ? fmaf(x1, sn, x2 * cs) : fmaf(x1, cs, -x2 * sn);
    ptr[tid] = out * post_scale;
}

// ---------------------------------------------------------------------------
// Kernel 3: causal attention (SIMT fp32, unchanged from R1)
// ---------------------------------------------------------------------------
#define SC_STRIDE 516
#define QT_STRIDE 68
#define V_STRIDE  132
#define SMEM_FLOATS (64 * SC_STRIDE + 128 * QT_STRIDE + 128 * QT_STRIDE)

__global__ __launch_bounds__(256)
void attention_kernel(const float* __restrict__ Q, const float* __restrict__ K,
                      const float* __restrict__ V, float* __restrict__ O) {
    extern __shared__ float smem[];
    float* scores = smem;                       // 64 x 516
    float* Qs = scores + 64 * SC_STRIDE;        // 128 x 68
    float* KVs = Qs + 128 * QT_STRIDE;          // 128 x 68 (or 64 x 132)

    const int tid = threadIdx.x;
    const int tx = tid & 15;
    const int ty = tid >> 4;
    const int qt = blockIdx.x;
    const int bh = blockIdx.y;
    const int b = bh / NHEADS;
    const int h = bh % NHEADS;
    const int g = h / PPG;

    const float* Qbase = Q + (size_t)b * SEQ * DMODEL + (size_t)h * HEADD;
    const float* Kbase = K + (size_t)b * SEQ * KVD + (size_t)g * HEADD;
    const float* Vbase = V + (size_t)b * SEQ * KVD + (size_t)g * HEADD;

    for (int i = tid; i < 64 * 128; i += 256) {
        int r = i >> 7, k = i & 127;
        Qs[k * QT_STRIDE + r] = Qbase[(size_t)(qt * 64 + r) * DMODEL + k];
    }

    // ---------------- phase 1: scores ----------------
    for (int kt = 0; kt <= qt; kt++) {
        __syncthreads();
        for (int i = tid; i < 64 * 128; i += 256) {
            int r = i >> 7, k = i & 127;
            KVs[k * QT_STRIDE + r] = Kbase[(size_t)(kt * 64 + r) * KVD + k];
        }
        __syncthreads();

        float acc[4][4];
        #pragma unroll
        for (int i = 0; i < 4; i++)
            #pragma unroll
            for (int j = 0; j < 4; j++) acc[i][j] = 0.0f;

        #pragma unroll 4
        for (int kk = 0; kk < 128; kk++) {
            float4 a = *reinterpret_cast<float4*>(&Qs[kk * QT_STRIDE + ty * 4]);
            float4 bb = *reinterpret_cast<float4*>(&KVs[kk * QT_STRIDE + tx * 4]);
            float ar[4] = {a.x, a.y, a.z, a.w};
            float br[4] = {bb.x, bb.y, bb.z, bb.w};
            #pragma unroll
            for (int i = 0; i < 4; i++)
                #pragma unroll
                for (int j = 0; j < 4; j++)
                    acc[i][j] = fmaf(ar[i], br[j], acc[i][j]);
        }

        #pragma unroll
        for (int i = 0; i < 4; i++) {
            int r = ty * 4 + i;
            int grow = qt * 64 + r;
            #pragma unroll
            for (int j = 0; j < 4; j++) {
                int c = tx * 4 + j;
                int gcol = kt * 64 + c;
                float val = (gcol <= grow) ? acc[i][j] * INV_SQRT_HD : -1e30f;
                scores[r * SC_STRIDE + kt * 64 + c] = val;
            }
        }
    }
    __syncthreads();

    // ---------------- phase 2: softmax ----------------
    const int ncols = (qt + 1) * 64;
    const int warp = tid >> 5;
    const int lane = tid & 31;
    for (int r = warp; r < 64; r += 8) {
        float* row = &scores[r * SC_STRIDE];
        float m = -1e30f;
        for (int c = lane; c < ncols; c += 32) m = fmaxf(m, row[c]);
        #pragma unroll
        for (int o = 16; o > 0; o >>= 1) m = fmaxf(m, __shfl_xor_sync(0xffffffffu, m, o));
        float sum = 0.0f;
        for (int c = lane; c < ncols; c += 32) {
            float e = __expf(row[c] - m);
            row[c] = e;
            sum += e;
        }
        #pragma unroll
        for (int o = 16; o > 0; o >>= 1) sum += __shfl_xor_sync(0xffffffffu, sum, o);
        float inv = 1.0f / sum;
        for (int c = lane; c < ncols; c += 32) row[c] *= inv;
    }
    __syncthreads();

    // ---------------- phase 3: O = P @ V ----------------
    float oacc[4][8];
    #pragma unroll
    for (int i = 0; i < 4; i++)
        #pragma unroll
        for (int j = 0; j < 8; j++) oacc[i][j] = 0.0f;

    for (int kt = 0; kt <= qt; kt++) {
        __syncthreads();
        for (int i = tid; i < 64 * 128; i += 256) {
            int r = i >> 7, c = i & 127;
            KVs[r * V_STRIDE + c] = Vbase[(size_t)(kt * 64 + r) * KVD + c];
        }
        __syncthreads();

        #pragma unroll 2
        for (int kk = 0; kk < 64; kk++) {
            float p[4];
            #pragma unroll
            for (int i = 0; i < 4; i++)
                p[i] = scores[(ty * 4 + i) * SC_STRIDE + kt * 64 + kk];
            float4 v0 = *reinterpret_cast<float4*>(&KVs[kk * V_STRIDE + tx * 8]);
            float4 v1 = *reinterpret_cast<float4*>(&KVs[kk * V_STRIDE + tx * 8 + 4]);
            float vr[8] = {v0.x, v0.y, v0.z, v0.w, v1.x, v1.y, v1.z, v1.w};
            #pragma unroll
            for (int i = 0; i < 4; i++)
                #pragma unroll
                for (int j = 0; j < 8; j++)
                    oacc[i][j] = fmaf(p[i], vr[j], oacc[i][j]);
        }
    }

    #pragma unroll
    for (int i = 0; i < 4; i++) {
        int srow = qt * 64 + ty * 4 + i;
        float* dst = &g_attn[((size_t)b * SEQ + srow) * DMODEL + h * HEADD + tx * 8];
        float4 c0 = make_float4(oacc[i][0], oacc[i][1], oacc[i][2], oacc[i][3]);
        float4 c1 = make_float4(oacc[i][4], oacc[i][5], oacc[i][6], oacc[i][7]);
        *reinterpret_cast<float4*>(dst) = c0;
        *reinterpret_cast<float4*>(dst + 4) = c1;
    }
}

// ---------------------------------------------------------------------------
// Launch
// ---------------------------------------------------------------------------
extern "C" void kernel_launch(void* const* d_in, const int* in_sizes, int n_in,
                              void* d_out, int out_size) {
    const float* x  = (const float*)d_in[0];
    const float* Wq = (const float*)d_in[1];
    const float* bq = (const float*)d_in[2];
    const float* Wk = (const float*)d_in[3];
    const float* bk = (const float*)d_in[4];
    const float* Wv = (const float*)d_in[5];
    const float* bv = (const float*)d_in[6];
    const float* Wo = (const float*)d_in[7];
    const float* bo = (const float*)d_in[8];
    const float* qns = (const float*)d_in[9];
    const float* kns = (const float*)d_in[10];
    float* out = (float*)d_out;

    float *qb, *kb, *vb, *ab;
    cudaGetSymbolAddress((void**)&qb, g_q);
    cudaGetSymbolAddress((void**)&kb, g_k);
    cudaGetSymbolAddress((void**)&vb, g_v);
    cudaGetSymbolAddress((void**)&ab, g_attn);

    // QKV projections (TF32 tensor cores)
    tf32_gemm_bias<<<dim3(DMODEL / 128, MROWS / 128), 256>>>(x, Wq, bq, qb, MROWS, DMODEL, DMODEL);
    tf32_gemm_bias<<<dim3(KVD / 128,    MROWS / 128), 256>>>(x, Wk, bk, kb, MROWS, KVD, DMODEL);
    tf32_gemm_bias<<<dim3(KVD / 128,    MROWS / 128), 256>>>(x, Wv, bv, vb, MROWS, KVD, DMODEL);

    // RMSNorm + RoPE
    rmsnorm_rope_kernel<<<BATCH * SEQ * NHEADS, 128>>>(qb, qns, NHEADS, INV_SQRT_HD);
    rmsnorm_rope_kernel<<<BATCH * SEQ * NGROUPS, 128>>>(kb, kns, NGROUPS, 1.0f);

    // Attention (fp32 SIMT)
    static const size_t smem_bytes = (size_t)SMEM_FLOATS * sizeof(float);
    cudaFuncSetAttribute(attention_kernel, cudaFuncAttributeMaxDynamicSharedMemorySize,
                         (int)smem_bytes);
    attention_kernel<<<dim3(SEQ / 64, BATCH * NHEADS), 256, smem_bytes>>>(qb, kb, vb, ab);

    // Output projection (TF32 tensor cores)
    tf32_gemm_bias<<<dim3(DMODEL / 128, MROWS / 128), 256>>>(ab, Wo, bo, out, MROWS, DMODEL, DMODEL);
}

// round 5
// speedup vs baseline: 2.5033x; 1.8037x over previous
#include <cuda_runtime.h>
#include <cuda_bf16.h>
#include <math.h>
#include <stdint.h>

// Problem constants
#define BATCH 16
#define SEQ   512
#define DMODEL 2048
#define NHEADS 16
#define NGROUPS 4
#define HEADD 128
#define PPG   (NHEADS / NGROUPS)   // 4
#define KVD   (NGROUPS * HEADD)    // 512
#define KVROW 1024                 // fused K|V row width
#define MROWS (BATCH * SEQ)        // 8192

#define INV_SQRT_HD 0.08838834764831845f
#define LN10000 9.210340371976184f

// ---------------------------------------------------------------------------
// Scratch buffers (static __device__, allocation-free)
// ---------------------------------------------------------------------------
__device__ float g_q[(size_t)MROWS * DMODEL];      // 64 MB
__device__ float g_kv[(size_t)MROWS * KVROW];      // 32 MB  (K | V per row)
__device__ float g_attn[(size_t)MROWS * DMODEL];   // 64 MB (tf32-rounded)
__device__ float g_xr[(size_t)MROWS * DMODEL];     // 64 MB (tf32-rounded x)
__device__ float g_wqt[(size_t)DMODEL * DMODEL];   // 16 MB  WqT [N,K]
__device__ float g_wkvt[(size_t)KVROW * DMODEL];   // 8 MB   [WkT ; WvT]
__device__ float g_wot[(size_t)DMODEL * DMODEL];   // 16 MB
__device__ float g_bkv[KVROW];

// ---------------------------------------------------------------------------
// helpers
// ---------------------------------------------------------------------------
__device__ __forceinline__ unsigned f2tf32(float x) {
    unsigned r;
    asm("cvt.rna.tf32.f32 %0, %1;" : "=r"(r) : "f"(x));
    return r;
}
__device__ __forceinline__ float rna_tf32f(float x) { return __uint_as_float(f2tf32(x)); }

__device__ __forceinline__ uint32_t smem_u32(const void* p) {
    uint32_t a;
    asm("{ .reg .u64 t; cvta.to.shared.u64 t, %1; cvt.u32.u64 %0, t; }" : "=r"(a) : "l"(p));
    return a;
}
__device__ __forceinline__ void cp16(uint32_t saddr, const void* g) {
    asm volatile("cp.async.cg.shared.global [%0], [%1], 16;" :: "r"(saddr), "l"(g));
}
__device__ __forceinline__ void cp_commit() { asm volatile("cp.async.commit_group;" ::: "memory"); }

__device__ __forceinline__ void ldsm_x4(uint32_t a[4], uint32_t addr) {
    asm volatile("ldmatrix.sync.aligned.m8n8.x4.shared.b16 {%0,%1,%2,%3}, [%4];"
                 : "=r"(a[0]), "=r"(a[1]), "=r"(a[2]), "=r"(a[3]) : "r"(addr));
}
__device__ __forceinline__ void ldsm_x2(uint32_t a[2], uint32_t addr) {
    asm volatile("ldmatrix.sync.aligned.m8n8.x2.shared.b16 {%0,%1}, [%2];"
                 : "=r"(a[0]), "=r"(a[1]) : "r"(addr));
}

__device__ __forceinline__ void mma_tf32(float c[4], const uint32_t a[4], const uint32_t b[2]) {
    asm volatile(
        "mma.sync.aligned.m16n8k8.row.col.f32.tf32.tf32.f32 "
        "{%0,%1,%2,%3}, {%4,%5,%6,%7}, {%8,%9}, {%0,%1,%2,%3};"
        : "+f"(c[0]), "+f"(c[1]), "+f"(c[2]), "+f"(c[3])
        : "r"(a[0]), "r"(a[1]), "r"(a[2]), "r"(a[3]), "r"(b[0]), "r"(b[1]));
}

// ---------------------------------------------------------------------------
// Pre-pass kernels
// ---------------------------------------------------------------------------
__global__ void round_x_kernel(const float* __restrict__ x, float* __restrict__ xr, int n4) {
    int i = blockIdx.x * blockDim.x + threadIdx.x;
    if (i < n4) {
        float4 v = reinterpret_cast<const float4*>(x)[i];
        v.x = rna_tf32f(v.x); v.y = rna_tf32f(v.y);
        v.z = rna_tf32f(v.z); v.w = rna_tf32f(v.w);
        reinterpret_cast<float4*>(xr)[i] = v;
    }
}

// WT[n][k] = round(W[k][n]);  W is [K,N]
__global__ void transpose_round_kernel(const float* __restrict__ W, float* __restrict__ WT,
                                       int K, int N) {
    __shared__ float t[32][33];
    int n0 = blockIdx.x * 32, k0 = blockIdx.y * 32;
    int tx = threadIdx.x, ty = threadIdx.y;
    #pragma unroll
    for (int j = 0; j < 32; j += 8)
        t[ty + j][tx] = W[(size_t)(k0 + ty + j) * N + n0 + tx];
    __syncthreads();
    #pragma unroll
    for (int j = 0; j < 32; j += 8)
        WT[(size_t)(n0 + ty + j) * K + k0 + tx] = rna_tf32f(t[tx][ty + j]);
}

__global__ void concat_bias_kernel(const float* __restrict__ bk, const float* __restrict__ bv,
                                   float* __restrict__ bkv) {
    int i = blockIdx.x * blockDim.x + threadIdx.x;
    if (i < KVROW) bkv[i] = (i < KVD) ? bk[i] : bv[i - KVD];
}

// ---------------------------------------------------------------------------
// TF32 mma.sync GEMM: C[M,N] = A[M,K] @ BT[N,K]^T + bias[N]
// CTA 128x128, BK=32, 3-stage cp.async, ldmatrix fragments.
// A, BT must be tf32-pre-rounded. M%128==0, N%128==0, K%32==0.
// ---------------------------------------------------------------------------
#define BK 32
#define STAGE_BYTES 32768          // A 16KB + B 16KB
#define GSM_B_OFF 16384
#define GEMM_SMEM_BYTES (3 * STAGE_BYTES)   // 98304

// swizzled smem offset for (row, 16B-chunk)
__device__ __forceinline__ uint32_t swz(int r, int chunk) {
    return (uint32_t)(r * 128 + ((chunk ^ (r & 7)) << 4));
}

__device__ __forceinline__ void gemm_load_stage(const float* __restrict__ A,
                                                const float* __restrict__ BT,
                                                int K, int m0, int n0, int kt,
                                                uint32_t sstage, int tid) {
    const int kbase = kt * BK;
    #pragma unroll
    for (int j = 0; j < 4; j++) {          // A: 128 rows x 8 chunks
        int i = tid + j * 256;
        int r = i >> 3, cc = i & 7;
        cp16(sstage + swz(r, cc), A + (size_t)(m0 + r) * K + kbase + cc * 4);
    }
    #pragma unroll
    for (int j = 0; j < 4; j++) {          // B: 128 rows x 8 chunks
        int i = tid + j * 256;
        int r = i >> 3, cc = i & 7;
        cp16(sstage + GSM_B_OFF + swz(r, cc), BT + (size_t)(n0 + r) * K + kbase + cc * 4);
    }
}

__global__ __launch_bounds__(256, 2)
void tf32_gemm_pipe(const float* __restrict__ A, const float* __restrict__ BT,
                    const float* __restrict__ bias, float* __restrict__ C,
                    int M, int N, int K) {
    extern __shared__ char smem[];
    const uint32_t sbase = smem_u32(smem);
    const int tid = threadIdx.x;
    const int lane = tid & 31;
    const int wid = tid >> 5;
    const int warpRow = (wid >> 2) * 64;
    const int warpCol = (wid & 3) * 32;
    const int m0 = blockIdx.y * 128;
    const int n0 = blockIdx.x * 128;

    float acc[4][4][4];
    #pragma unroll
    for (int i = 0; i < 4; i++)
        #pragma unroll
        for (int j = 0; j < 4; j++)
            #pragma unroll
            for (int r = 0; r < 4; r++) acc[i][j][r] = 0.0f;

    const int NT = K / BK;

    // per-thread ldmatrix address components
    const int a_sub = lane >> 3;               // 0..3
    const int a_row_in = (lane & 7) + (a_sub & 1) * 8;
    const int a_chunk_add = a_sub >> 1;        // 0 or 1
    const int b_sub = (lane >> 3) & 1;         // 0..1 (lanes 16-31 mirror 0-15)
    const int b_row_in = lane & 7;

    // prologue: stages 0,1
    gemm_load_stage(A, BT, K, m0, n0, 0, sbase, tid);
    cp_commit();
    gemm_load_stage(A, BT, K, m0, n0, 1, sbase + STAGE_BYTES, tid);
    cp_commit();

    for (int kt = 0; kt < NT; kt++) {
        if (kt + 2 < NT) {
            asm volatile("cp.async.wait_group 1;" ::: "memory");
        } else {
            asm volatile("cp.async.wait_group 0;" ::: "memory");
        }
        __syncthreads();
        if (kt + 2 < NT) {
            gemm_load_stage(A, BT, K, m0, n0, kt + 2,
                            sbase + ((kt + 2) % 3) * STAGE_BYTES, tid);
            cp_commit();
        }

        const uint32_t sA = sbase + (kt % 3) * STAGE_BYTES;
        const uint32_t sB = sA + GSM_B_OFF;

        #pragma unroll
        for (int ks = 0; ks < 4; ks++) {
            uint32_t af[4][4];
            uint32_t bf[4][2];
            #pragma unroll
            for (int it = 0; it < 4; it++) {
                int r = warpRow + it * 16 + a_row_in;
                int chunk = ks * 2 + a_chunk_add;
                ldsm_x4(af[it], sA + swz(r, chunk));
            }
            #pragma unroll
            for (int jt = 0; jt < 4; jt++) {
                int r = warpCol + jt * 8 + b_row_in;
                int chunk = ks * 2 + b_sub;
                ldsm_x2(bf[jt], sB + swz(r, chunk));
            }
            #pragma unroll
            for (int it = 0; it < 4; it++)
                #pragma unroll
                for (int jt = 0; jt < 4; jt++)
                    mma_tf32(acc[it][jt], af[it], bf[jt]);
        }
    }

    // epilogue with bias
    const int lr = lane >> 2;
    const int lc = lane & 3;
    #pragma unroll
    for (int it = 0; it < 4; it++) {
        #pragma unroll
        for (int jt = 0; jt < 4; jt++) {
            int row = m0 + warpRow + it * 16 + lr;
            int col = n0 + warpCol + jt * 8 + 2 * lc;
            float b0 = bias[col];
            float b1 = bias[col + 1];
            float2 v0 = make_float2(acc[it][jt][0] + b0, acc[it][jt][1] + b1);
            float2 v1 = make_float2(acc[it][jt][2] + b0, acc[it][jt][3] + b1);
            *reinterpret_cast<float2*>(&C[(size_t)row * N + col]) = v0;
            *reinterpret_cast<float2*>(&C[(size_t)(row + 8) * N + col]) = v1;
        }
    }
}

// ---------------------------------------------------------------------------
// fused RMSNorm + RoPE (in-place) on one 128-vector
// block i -> row = i / heads_per_row, head = i % heads_per_row
// ptr = buf + row*rowstride + head*128;  s = row % SEQ
// ---------------------------------------------------------------------------
__global__ __launch_bounds__(128)
void rmsnorm_rope_kernel(float* __restrict__ buf, const float* __restrict__ scale,
                         int heads_per_row, int rowstride, float post_scale) {
    __shared__ float sh[128];
    __shared__ float red[4];
    const int tid = threadIdx.x;
    const int row = blockIdx.x / heads_per_row;
    const int head = blockIdx.x % heads_per_row;
    float* ptr = buf + (size_t)row * rowstride + head * HEADD;
    const int s = row % SEQ;

    float v = ptr[tid];
    float sq = v * v;
    #pragma unroll
    for (int o = 16; o > 0; o >>= 1) sq += __shfl_xor_sync(0xffffffffu, sq, o);
    if ((tid & 31) == 0) red[tid >> 5] = sq;
    __syncthreads();
    float total = red[0] + red[1] + red[2] + red[3];
    float r = rsqrtf(total * (1.0f / 128.0f) + 1e-6f);
    sh[tid] = v * r * scale[tid];
    __syncthreads();

    const int ip = tid >> 1;
    float x1 = sh[ip * 2];
    float x2 = sh[ip * 2 + 1];
    float inv_freq = expf((float)ip * (-LN10000 / 64.0f));
    float ang = (float)s * inv_freq;
    float sn, cs;
    sincosf(ang, &sn, &cs);
    float out = (tid & 1) ? fmaf(x1, sn, x2 * cs) : fmaf(x1, cs, -x2 * sn);
    ptr[tid] = out * post_scale;
}

// ---------------------------------------------------------------------------
// causal attention (SIMT fp32); K,V from fused g_kv rows; output tf32-rounded
// ---------------------------------------------------------------------------
#define SC_STRIDE 516
#define QT_STRIDE 68
#define V_STRIDE  132
#define SMEM_FLOATS (64 * SC_STRIDE + 128 * QT_STRIDE + 128 * QT_STRIDE)

__global__ __launch_bounds__(256)
void attention_kernel(const float* __restrict__ Q, const float* __restrict__ KV,
                      float* __restrict__ O) {
    extern __shared__ float smemf[];
    float* scores = smemf;
    float* Qs = scores + 64 * SC_STRIDE;
    float* KVs = Qs + 128 * QT_STRIDE;

    const int tid = threadIdx.x;
    const int tx = tid & 15;
    const int ty = tid >> 4;
    const int qt = blockIdx.x;
    const int bh = blockIdx.y;
    const int b = bh / NHEADS;
    const int h = bh % NHEADS;
    const int g = h / PPG;

    const float* Qbase = Q + (size_t)b * SEQ * DMODEL + (size_t)h * HEADD;
    const float* Kbase = KV + (size_t)b * SEQ * KVROW + (size_t)g * HEADD;
    const float* Vbase = KV + (size_t)b * SEQ * KVROW + KVD + (size_t)g * HEADD;

    for (int i = tid; i < 64 * 128; i += 256) {
        int r = i >> 7, k = i & 127;
        Qs[k * QT_STRIDE + r] = Qbase[(size_t)(qt * 64 + r) * DMODEL + k];
    }

    for (int kt = 0; kt <= qt; kt++) {
        __syncthreads();
        for (int i = tid; i < 64 * 128; i += 256) {
            int r = i >> 7, k = i & 127;
            KVs[k * QT_STRIDE + r] = Kbase[(size_t)(kt * 64 + r) * KVROW + k];
        }
        __syncthreads();

        float acc[4][4];
        #pragma unroll
        for (int i = 0; i < 4; i++)
            #pragma unroll
            for (int j = 0; j < 4; j++) acc[i][j] = 0.0f;

        #pragma unroll 4
        for (int kk = 0; kk < 128; kk++) {
            float4 a = *reinterpret_cast<float4*>(&Qs[kk * QT_STRIDE + ty * 4]);
            float4 bb = *reinterpret_cast<float4*>(&KVs[kk * QT_STRIDE + tx * 4]);
            float ar[4] = {a.x, a.y, a.z, a.w};
            float br[4] = {bb.x, bb.y, bb.z, bb.w};
            #pragma unroll
            for (int i = 0; i < 4; i++)
                #pragma unroll
                for (int j = 0; j < 4; j++)
                    acc[i][j] = fmaf(ar[i], br[j], acc[i][j]);
        }

        #pragma unroll
        for (int i = 0; i < 4; i++) {
            int r = ty * 4 + i;
            int grow = qt * 64 + r;
            #pragma unroll
            for (int j = 0; j < 4; j++) {
                int c = tx * 4 + j;
                int gcol = kt * 64 + c;
                float val = (gcol <= grow) ? acc[i][j] * INV_SQRT_HD : -1e30f;
                scores[r * SC_STRIDE + kt * 64 + c] = val;
            }
        }
    }
    __syncthreads();

    const int ncols = (qt + 1) * 64;
    const int warp = tid >> 5;
    const int lane = tid & 31;
    for (int r = warp; r < 64; r += 8) {
        float* row = &scores[r * SC_STRIDE];
        float m = -1e30f;
        for (int c = lane; c < ncols; c += 32) m = fmaxf(m, row[c]);
        #pragma unroll
        for (int o = 16; o > 0; o >>= 1) m = fmaxf(m, __shfl_xor_sync(0xffffffffu, m, o));
        float sum = 0.0f;
        for (int c = lane; c < ncols; c += 32) {
            float e = __expf(row[c] - m);
            row[c] = e;
            sum += e;
        }
        #pragma unroll
        for (int o = 16; o > 0; o >>= 1) sum += __shfl_xor_sync(0xffffffffu, sum, o);
        float inv = 1.0f / sum;
        for (int c = lane; c < ncols; c += 32) row[c] *= inv;
    }
    __syncthreads();

    float oacc[4][8];
    #pragma unroll
    for (int i = 0; i < 4; i++)
        #pragma unroll
        for (int j = 0; j < 8; j++) oacc[i][j] = 0.0f;

    for (int kt = 0; kt <= qt; kt++) {
        __syncthreads();
        for (int i = tid; i < 64 * 128; i += 256) {
            int r = i >> 7, c = i & 127;
            KVs[r * V_STRIDE + c] = Vbase[(size_t)(kt * 64 + r) * KVROW + c];
        }
        __syncthreads();

        #pragma unroll 2
        for (int kk = 0; kk < 64; kk++) {
            float p[4];
            #pragma unroll
            for (int i = 0; i < 4; i++)
                p[i] = scores[(ty * 4 + i) * SC_STRIDE + kt * 64 + kk];
            float4 v0 = *reinterpret_cast<float4*>(&KVs[kk * V_STRIDE + tx * 8]);
            float4 v1 = *reinterpret_cast<float4*>(&KVs[kk * V_STRIDE + tx * 8 + 4]);
            float vr[8] = {v0.x, v0.y, v0.z, v0.w, v1.x, v1.y, v1.z, v1.w};
            #pragma unroll
            for (int i = 0; i < 4; i++)
                #pragma unroll
                for (int j = 0; j < 8; j++)
                    oacc[i][j] = fmaf(p[i], vr[j], oacc[i][j]);
        }
    }

    #pragma unroll
    for (int i = 0; i < 4; i++) {
        int srow = qt * 64 + ty * 4 + i;
        float* dst = &O[((size_t)b * SEQ + srow) * DMODEL + h * HEADD + tx * 8];
        float4 c0 = make_float4(rna_tf32f(oacc[i][0]), rna_tf32f(oacc[i][1]),
                                rna_tf32f(oacc[i][2]), rna_tf32f(oacc[i][3]));
        float4 c1 = make_float4(rna_tf32f(oacc[i][4]), rna_tf32f(oacc[i][5]),
                                rna_tf32f(oacc[i][6]), rna_tf32f(oacc[i][7]));
        *reinterpret_cast<float4*>(dst) = c0;
        *reinterpret_cast<float4*>(dst + 4) = c1;
    }
}

// ---------------------------------------------------------------------------
// Launch
// ---------------------------------------------------------------------------
extern "C" void kernel_launch(void* const* d_in, const int* in_sizes, int n_in,
                              void* d_out, int out_size) {
    const float* x  = (const float*)d_in[0];
    const float* Wq = (const float*)d_in[1];
    const float* bq = (const float*)d_in[2];
    const float* Wk = (const float*)d_in[3];
    const float* bk = (const float*)d_in[4];
    const float* Wv = (const float*)d_in[5];
    const float* bv = (const float*)d_in[6];
    const float* Wo = (const float*)d_in[7];
    const float* bo = (const float*)d_in[8];
    const float* qns = (const float*)d_in[9];
    const float* kns = (const float*)d_in[10];
    float* out = (float*)d_out;

    float *qb, *kvb, *ab, *xr, *wqt, *wkvt, *wot, *bkv;
    cudaGetSymbolAddress((void**)&qb, g_q);
    cudaGetSymbolAddress((void**)&kvb, g_kv);
    cudaGetSymbolAddress((void**)&ab, g_attn);
    cudaGetSymbolAddress((void**)&xr, g_xr);
    cudaGetSymbolAddress((void**)&wqt, g_wqt);
    cudaGetSymbolAddress((void**)&wkvt, g_wkvt);
    cudaGetSymbolAddress((void**)&wot, g_wot);
    cudaGetSymbolAddress((void**)&bkv, g_bkv);

    // Pre-pass: tf32-round x; transpose+round weights to [N,K]; fuse K|V
    {
        int n4 = MROWS * DMODEL / 4;
        round_x_kernel<<<(n4 + 255) / 256, 256>>>(x, xr, n4);
        dim3 tb(32, 8);
        transpose_round_kernel<<<dim3(DMODEL / 32, DMODEL / 32), tb>>>(Wq, wqt, DMODEL, DMODEL);
        transpose_round_kernel<<<dim3(KVD / 32, DMODEL / 32), tb>>>(Wk, wkvt, DMODEL, KVD);
        transpose_round_kernel<<<dim3(KVD / 32, DMODEL / 32), tb>>>(Wv, wkvt + (size_t)KVD * DMODEL,
                                                                    DMODEL, KVD);
        transpose_round_kernel<<<dim3(DMODEL / 32, DMODEL / 32), tb>>>(Wo, wot, DMODEL, DMODEL);
        concat_bias_kernel<<<4, 256>>>(bk, bv, bkv);
    }

    cudaFuncSetAttribute(tf32_gemm_pipe, cudaFuncAttributeMaxDynamicSharedMemorySize,
                         GEMM_SMEM_BYTES);

    // Q projection and fused K|V projection
    tf32_gemm_pipe<<<dim3(DMODEL / 128, MROWS / 128), 256, GEMM_SMEM_BYTES>>>(
        xr, wqt, bq, qb, MROWS, DMODEL, DMODEL);
    tf32_gemm_pipe<<<dim3(KVROW / 128, MROWS / 128), 256, GEMM_SMEM_BYTES>>>(
        xr, wkvt, bkv, kvb, MROWS, KVROW, DMODEL);

    // RMSNorm + RoPE (q: 16 heads/row stride 2048; k: first 4 head-slots of kv rows)
    rmsnorm_rope_kernel<<<MROWS * NHEADS, 128>>>(qb, qns, NHEADS, DMODEL, INV_SQRT_HD);
    rmsnorm_rope_kernel<<<MROWS * NGROUPS, 128>>>(kvb, kns, NGROUPS, KVROW, 1.0f);

    // Attention
    static const size_t attn_smem = (size_t)SMEM_FLOATS * sizeof(float);
    cudaFuncSetAttribute(attention_kernel, cudaFuncAttributeMaxDynamicSharedMemorySize,
                         (int)attn_smem);
    attention_kernel<<<dim3(SEQ / 64, BATCH * NHEADS), 256, attn_smem>>>(qb, kvb, ab);

    // Output projection
    tf32_gemm_pipe<<<dim3(DMODEL / 128, MROWS / 128), 256, GEMM_SMEM_BYTES>>>(
        ab, wot, bo, out, MROWS, DMODEL, DMODEL);
}

// round 6
// speedup vs baseline: 4.0050x; 1.5999x over previous
#include <cuda_runtime.h>
#include <cuda_bf16.h>
#include <math.h>
#include <stdint.h>

// Problem constants
#define BATCH 16
#define SEQ   512
#define DMODEL 2048
#define NHEADS 16
#define NGROUPS 4
#define HEADD 128
#define PPG   (NHEADS / NGROUPS)   // 4
#define KVD   (NGROUPS * HEADD)    // 512
#define KVROW 1024                 // fused K|V row width
#define MROWS (BATCH * SEQ)        // 8192

#define INV_SQRT_HD 0.08838834764831845f
#define LN10000 9.210340371976184f

// ---------------------------------------------------------------------------
// Scratch buffers (static __device__, allocation-free)
// ---------------------------------------------------------------------------
__device__ float g_q[(size_t)MROWS * DMODEL];      // 64 MB
__device__ float g_kv[(size_t)MROWS * KVROW];      // 32 MB  (K | V per row)
__device__ float g_attn[(size_t)MROWS * DMODEL];   // 64 MB (tf32-rounded)
__device__ float g_xr[(size_t)MROWS * DMODEL];     // 64 MB (tf32-rounded x)
__device__ float g_wqt[(size_t)DMODEL * DMODEL];   // 16 MB  WqT [N,K]
__device__ float g_wkvt[(size_t)KVROW * DMODEL];   // 8 MB   [WkT ; WvT]
__device__ float g_wot[(size_t)DMODEL * DMODEL];   // 16 MB
__device__ float g_bkv[KVROW];

// ---------------------------------------------------------------------------
// helpers
// ---------------------------------------------------------------------------
__device__ __forceinline__ unsigned f2tf32(float x) {
    unsigned r;
    asm("cvt.rna.tf32.f32 %0, %1;" : "=r"(r) : "f"(x));
    return r;
}
__device__ __forceinline__ float rna_tf32f(float x) { return __uint_as_float(f2tf32(x)); }

__device__ __forceinline__ uint32_t smem_u32(const void* p) {
    uint32_t a;
    asm("{ .reg .u64 t; cvta.to.shared.u64 t, %1; cvt.u32.u64 %0, t; }" : "=r"(a) : "l"(p));
    return a;
}
__device__ __forceinline__ void cp16(uint32_t saddr, const void* g) {
    asm volatile("cp.async.cg.shared.global [%0], [%1], 16;" :: "r"(saddr), "l"(g));
}
__device__ __forceinline__ void cp_commit() { asm volatile("cp.async.commit_group;" ::: "memory"); }

__device__ __forceinline__ void ldsm_x4(uint32_t a[4], uint32_t addr) {
    asm volatile("ldmatrix.sync.aligned.m8n8.x4.shared.b16 {%0,%1,%2,%3}, [%4];"
                 : "=r"(a[0]), "=r"(a[1]), "=r"(a[2]), "=r"(a[3]) : "r"(addr));
}
__device__ __forceinline__ void ldsm_x2(uint32_t a[2], uint32_t addr) {
    asm volatile("ldmatrix.sync.aligned.m8n8.x2.shared.b16 {%0,%1}, [%2];"
                 : "=r"(a[0]), "=r"(a[1]) : "r"(addr));
}

__device__ __forceinline__ void mma_tf32(float c[4], const uint32_t a[4], const uint32_t b[2]) {
    asm volatile(
        "mma.sync.aligned.m16n8k8.row.col.f32.tf32.tf32.f32 "
        "{%0,%1,%2,%3}, {%4,%5,%6,%7}, {%8,%9}, {%0,%1,%2,%3};"
        : "+f"(c[0]), "+f"(c[1]), "+f"(c[2]), "+f"(c[3])
        : "r"(a[0]), "r"(a[1]), "r"(a[2]), "r"(a[3]), "r"(b[0]), "r"(b[1]));
}

// ---------------------------------------------------------------------------
// Pre-pass kernels
// ---------------------------------------------------------------------------
__global__ void round_x_kernel(const float* __restrict__ x, float* __restrict__ xr, int n4) {
    int i = blockIdx.x * blockDim.x + threadIdx.x;
    if (i < n4) {
        float4 v = reinterpret_cast<const float4*>(x)[i];
        v.x = rna_tf32f(v.x); v.y = rna_tf32f(v.y);
        v.z = rna_tf32f(v.z); v.w = rna_tf32f(v.w);
        reinterpret_cast<float4*>(xr)[i] = v;
    }
}

// WT[n][k] = round(W[k][n]);  W is [K,N]
__global__ void transpose_round_kernel(const float* __restrict__ W, float* __restrict__ WT,
                                       int K, int N) {
    __shared__ float t[32][33];
    int n0 = blockIdx.x * 32, k0 = blockIdx.y * 32;
    int tx = threadIdx.x, ty = threadIdx.y;
    #pragma unroll
    for (int j = 0; j < 32; j += 8)
        t[ty + j][tx] = W[(size_t)(k0 + ty + j) * N + n0 + tx];
    __syncthreads();
    #pragma unroll
    for (int j = 0; j < 32; j += 8)
        WT[(size_t)(n0 + ty + j) * K + k0 + tx] = rna_tf32f(t[tx][ty + j]);
}

__global__ void concat_bias_kernel(const float* __restrict__ bk, const float* __restrict__ bv,
                                   float* __restrict__ bkv) {
    int i = blockIdx.x * blockDim.x + threadIdx.x;
    if (i < KVROW) bkv[i] = (i < KVD) ? bk[i] : bv[i - KVD];
}

// ---------------------------------------------------------------------------
// TF32 mma.sync GEMM: C[M,N] = A[M,K] @ BT[N,K]^T + bias[N]
// CTA 128x128, BK=32, 3-stage cp.async, ldmatrix fragments.
// roundC: tf32-round the output (for values consumed by later tf32 GEMMs).
// ---------------------------------------------------------------------------
#define BK 32
#define STAGE_BYTES 32768          // A 16KB + B 16KB
#define GSM_B_OFF 16384
#define GEMM_SMEM_BYTES (3 * STAGE_BYTES)   // 98304

// swizzled smem offset for (row, 16B-chunk), 128B rows (chunk in [0,8))
__device__ __forceinline__ uint32_t swz(int r, int chunk) {
    return (uint32_t)(r * 128 + ((chunk ^ (r & 7)) << 4));
}

__device__ __forceinline__ void gemm_load_stage(const float* __restrict__ A,
                                                const float* __restrict__ BT,
                                                int K, int m0, int n0, int kt,
                                                uint32_t sstage, int tid) {
    const int kbase = kt * BK;
    #pragma unroll
    for (int j = 0; j < 4; j++) {          // A: 128 rows x 8 chunks
        int i = tid + j * 256;
        int r = i >> 3, cc = i & 7;
        cp16(sstage + swz(r, cc), A + (size_t)(m0 + r) * K + kbase + cc * 4);
    }
    #pragma unroll
    for (int j = 0; j < 4; j++) {          // B: 128 rows x 8 chunks
        int i = tid + j * 256;
        int r = i >> 3, cc = i & 7;
        cp16(sstage + GSM_B_OFF + swz(r, cc), BT + (size_t)(n0 + r) * K + kbase + cc * 4);
    }
}

__global__ __launch_bounds__(256, 2)
void tf32_gemm_pipe(const float* __restrict__ A, const float* __restrict__ BT,
                    const float* __restrict__ bias, float* __restrict__ C,
                    int M, int N, int K, int roundC) {
    extern __shared__ char smem[];
    const uint32_t sbase = smem_u32(smem);
    const int tid = threadIdx.x;
    const int lane = tid & 31;
    const int wid = tid >> 5;
    const int warpRow = (wid >> 2) * 64;
    const int warpCol = (wid & 3) * 32;
    const int m0 = blockIdx.y * 128;
    const int n0 = blockIdx.x * 128;

    float acc[4][4][4];
    #pragma unroll
    for (int i = 0; i < 4; i++)
        #pragma unroll
        for (int j = 0; j < 4; j++)
            #pragma unroll
            for (int r = 0; r < 4; r++) acc[i][j][r] = 0.0f;

    const int NT = K / BK;

    const int a_sub = lane >> 3;
    const int a_row_in = (lane & 7) + (a_sub & 1) * 8;
    const int a_chunk_add = a_sub >> 1;
    const int b_sub = (lane >> 3) & 1;
    const int b_row_in = lane & 7;

    gemm_load_stage(A, BT, K, m0, n0, 0, sbase, tid);
    cp_commit();
    gemm_load_stage(A, BT, K, m0, n0, 1, sbase + STAGE_BYTES, tid);
    cp_commit();

    for (int kt = 0; kt < NT; kt++) {
        if (kt + 2 < NT) {
            asm volatile("cp.async.wait_group 1;" ::: "memory");
        } else {
            asm volatile("cp.async.wait_group 0;" ::: "memory");
        }
        __syncthreads();
        if (kt + 2 < NT) {
            gemm_load_stage(A, BT, K, m0, n0, kt + 2,
                            sbase + ((kt + 2) % 3) * STAGE_BYTES, tid);
            cp_commit();
        }

        const uint32_t sA = sbase + (kt % 3) * STAGE_BYTES;
        const uint32_t sB = sA + GSM_B_OFF;

        #pragma unroll
        for (int ks = 0; ks < 4; ks++) {
            uint32_t af[4][4];
            uint32_t bf[4][2];
            #pragma unroll
            for (int it = 0; it < 4; it++) {
                int r = warpRow + it * 16 + a_row_in;
                int chunk = ks * 2 + a_chunk_add;
                ldsm_x4(af[it], sA + swz(r, chunk));
            }
            #pragma unroll
            for (int jt = 0; jt < 4; jt++) {
                int r = warpCol + jt * 8 + b_row_in;
                int chunk = ks * 2 + b_sub;
                ldsm_x2(bf[jt], sB + swz(r, chunk));
            }
            #pragma unroll
            for (int it = 0; it < 4; it++)
                #pragma unroll
                for (int jt = 0; jt < 4; jt++)
                    mma_tf32(acc[it][jt], af[it], bf[jt]);
        }
    }

    const int lr = lane >> 2;
    const int lc = lane & 3;
    #pragma unroll
    for (int it = 0; it < 4; it++) {
        #pragma unroll
        for (int jt = 0; jt < 4; jt++) {
            int row = m0 + warpRow + it * 16 + lr;
            int col = n0 + warpCol + jt * 8 + 2 * lc;
            float b0 = bias[col];
            float b1 = bias[col + 1];
            float2 v0 = make_float2(acc[it][jt][0] + b0, acc[it][jt][1] + b1);
            float2 v1 = make_float2(acc[it][jt][2] + b0, acc[it][jt][3] + b1);
            if (roundC) {
                v0.x = rna_tf32f(v0.x); v0.y = rna_tf32f(v0.y);
                v1.x = rna_tf32f(v1.x); v1.y = rna_tf32f(v1.y);
            }
            *reinterpret_cast<float2*>(&C[(size_t)row * N + col]) = v0;
            *reinterpret_cast<float2*>(&C[(size_t)(row + 8) * N + col]) = v1;
        }
    }
}

// ---------------------------------------------------------------------------
// fused RMSNorm + RoPE (in-place), output tf32-rounded
// ---------------------------------------------------------------------------
__global__ __launch_bounds__(128)
void rmsnorm_rope_kernel(float* __restrict__ buf, const float* __restrict__ scale,
                         int heads_per_row, int rowstride, float post_scale) {
    __shared__ float sh[128];
    __shared__ float red[4];
    const int tid = threadIdx.x;
    const int row = blockIdx.x / heads_per_row;
    const int head = blockIdx.x % heads_per_row;
    float* ptr = buf + (size_t)row * rowstride + head * HEADD;
    const int s = row % SEQ;

    float v = ptr[tid];
    float sq = v * v;
    #pragma unroll
    for (int o = 16; o > 0; o >>= 1) sq += __shfl_xor_sync(0xffffffffu, sq, o);
    if ((tid & 31) == 0) red[tid >> 5] = sq;
    __syncthreads();
    float total = red[0] + red[1] + red[2] + red[3];
    float r = rsqrtf(total * (1.0f / 128.0f) + 1e-6f);
    sh[tid] = v * r * scale[tid];
    __syncthreads();

    const int ip = tid >> 1;
    float x1 = sh[ip * 2];
    float x2 = sh[ip * 2 + 1];
    float inv_freq = expf((float)ip * (-LN10000 / 64.0f));
    float ang = (float)s * inv_freq;
    float sn, cs;
    sincosf(ang, &sn, &cs);
    float out = (tid & 1) ? fmaf(x1, sn, x2 * cs) : fmaf(x1, cs, -x2 * sn);
    ptr[tid] = rna_tf32f(out * post_scale);
}

// ---------------------------------------------------------------------------
// Tensor-core causal attention.
// block = (qt, b*h); 256 threads (8 warps).
// smem: scores[64][516] | Q tile (swizzled 512B rows) | KV region:
//   phase1: two K tiles (swizzled) double-buffered via cp.async
//   phase3: one V tile, plain stride-132 rows
// ---------------------------------------------------------------------------
#define ATT_SC_STRIDE 516
#define ATT_Q_OFF  (64 * ATT_SC_STRIDE * 4)            // 132096
#define ATT_KV_OFF (ATT_Q_OFF + 32768)                 // 164864
#define ATT_SMEM_BYTES (ATT_KV_OFF + 65536)            // 230400

// swizzled offset in a 512-byte-row tile; c = 16B chunk index in [0,32)
__device__ __forceinline__ uint32_t qswz(int r, int c) {
    return (uint32_t)(r * 512 + ((((c ^ r) & 7) | (c & 24)) << 4));
}

__global__ __launch_bounds__(256, 1)
void attention_tc_kernel(const float* __restrict__ Q, const float* __restrict__ KV,
                         float* __restrict__ O) {
    extern __shared__ char smemraw[];
    float* scores = reinterpret_cast<float*>(smemraw);
    float* Vs = reinterpret_cast<float*>(smemraw + ATT_KV_OFF);
    const uint32_t sbase = smem_u32(smemraw);
    const uint32_t sQ = sbase + ATT_Q_OFF;
    const uint32_t sKV = sbase + ATT_KV_OFF;

    const int tid = threadIdx.x;
    const int lane = tid & 31;
    const int wid = tid >> 5;
    const int qt = blockIdx.x;
    const int bh = blockIdx.y;
    const int b = bh / NHEADS;
    const int h = bh % NHEADS;
    const int g = h / PPG;

    const float* Qbase = Q + (size_t)b * SEQ * DMODEL + (size_t)h * HEADD;
    const float* Kbase = KV + (size_t)b * SEQ * KVROW + (size_t)g * HEADD;
    const float* Vbase = KV + (size_t)b * SEQ * KVROW + KVD + (size_t)g * HEADD;

    // ---- prologue: async-load Q tile and K tile 0 (both swizzled) ----
    #pragma unroll
    for (int j = 0; j < 8; j++) {
        int idx = tid + j * 256;
        int r = idx >> 5, c = idx & 31;
        cp16(sQ + qswz(r, c), Qbase + (size_t)(qt * 64 + r) * DMODEL + c * 4);
    }
    #pragma unroll
    for (int j = 0; j < 8; j++) {
        int idx = tid + j * 256;
        int r = idx >> 5, c = idx & 31;
        cp16(sKV + qswz(r, c), Kbase + (size_t)r * KVROW + c * 4);
    }
    cp_commit();
    asm volatile("cp.async.wait_group 0;" ::: "memory");
    __syncthreads();

    const int a_sub = lane >> 3;
    const int a_row_in = (lane & 7) + (a_sub & 1) * 8;
    const int a_chunk_add = a_sub >> 1;
    const int b_row_in = lane & 7;
    const int b_sub = (lane >> 3) & 1;
    const int lr = lane >> 2;
    const int lc = lane & 3;
    const int warpRowS = (wid & 3) * 16;
    const int warpColS = (wid >> 2) * 32;

    // ---------------- phase 1: scores = Q @ K^T (tensor cores) ----------------
    for (int kt = 0; kt <= qt; kt++) {
        const int buf = kt & 1;
        if (kt < qt) {
            #pragma unroll
            for (int j = 0; j < 8; j++) {
                int idx = tid + j * 256;
                int r = idx >> 5, c = idx & 31;
                cp16(sKV + (1 - buf) * 32768 + qswz(r, c),
                     Kbase + (size_t)((kt + 1) * 64 + r) * KVROW + c * 4);
            }
            cp_commit();
        }
        const uint32_t sK = sKV + buf * 32768;

        float acc[4][4];
        #pragma unroll
        for (int i = 0; i < 4; i++)
            #pragma unroll
            for (int j = 0; j < 4; j++) acc[i][j] = 0.0f;

        #pragma unroll
        for (int ks = 0; ks < 16; ks++) {
            uint32_t af[4];
            ldsm_x4(af, sQ + qswz(warpRowS + a_row_in, ks * 2 + a_chunk_add));
            #pragma unroll
            for (int jt = 0; jt < 4; jt++) {
                uint32_t bf[2];
                ldsm_x2(bf, sK + qswz(warpColS + jt * 8 + b_row_in, ks * 2 + b_sub));
                mma_tf32(acc[jt], af, bf);
            }
        }

        // epilogue: scale + causal mask -> scores
        #pragma unroll
        for (int jt = 0; jt < 4; jt++) {
            int r0 = warpRowS + lr;
            int r1 = r0 + 8;
            int c0 = kt * 64 + warpColS + jt * 8 + 2 * lc;
            int g0 = qt * 64 + r0;
            int g1 = qt * 64 + r1;
            float2 v0, v1;
            v0.x = (c0 <= g0) ? acc[jt][0] * INV_SQRT_HD : -1e30f;
            v0.y = (c0 + 1 <= g0) ? acc[jt][1] * INV_SQRT_HD : -1e30f;
            v1.x = (c0 <= g1) ? acc[jt][2] * INV_SQRT_HD : -1e30f;
            v1.y = (c0 + 1 <= g1) ? acc[jt][3] * INV_SQRT_HD : -1e30f;
            *reinterpret_cast<float2*>(&scores[r0 * ATT_SC_STRIDE + c0]) = v0;
            *reinterpret_cast<float2*>(&scores[r1 * ATT_SC_STRIDE + c0]) = v1;
        }
        if (kt < qt) asm volatile("cp.async.wait_group 0;" ::: "memory");
        __syncthreads();
    }

    // prefetch V tile 0 into the (now free) KV region, overlapping softmax
    #pragma unroll
    for (int j = 0; j < 8; j++) {
        int idx = tid + j * 256;
        int r = idx >> 5, c = idx & 31;
        cp16(sKV + r * 528 + c * 16, Vbase + (size_t)r * KVROW + c * 4);
    }
    cp_commit();

    // ---------------- phase 2: softmax (rounds P to tf32) ----------------
    {
        const int ncols = (qt + 1) * 64;
        for (int r = wid; r < 64; r += 8) {
            float* row = &scores[r * ATT_SC_STRIDE];
            float m = -1e30f;
            for (int c = lane; c < ncols; c += 32) m = fmaxf(m, row[c]);
            #pragma unroll
            for (int o = 16; o > 0; o >>= 1) m = fmaxf(m, __shfl_xor_sync(0xffffffffu, m, o));
            float sum = 0.0f;
            for (int c = lane; c < ncols; c += 32) {
                float e = __expf(row[c] - m);
                row[c] = e;
                sum += e;
            }
            #pragma unroll
            for (int o = 16; o > 0; o >>= 1) sum += __shfl_xor_sync(0xffffffffu, sum, o);
            float inv = 1.0f / sum;
            for (int c = lane; c < ncols; c += 32) row[c] = rna_tf32f(row[c] * inv);
        }
    }
    __syncthreads();

    // ---------------- phase 3: O = P @ V (tensor cores) ----------------
    const int warpRowO = (wid & 3) * 16;
    const int warpColO = (wid >> 2) * 64;
    float oacc[8][4];
    #pragma unroll
    for (int i = 0; i < 8; i++)
        #pragma unroll
        for (int j = 0; j < 4; j++) oacc[i][j] = 0.0f;

    for (int kt = 0; kt <= qt; kt++) {
        asm volatile("cp.async.wait_group 0;" ::: "memory");
        __syncthreads();   // V[kt] fully in smem for all threads

        #pragma unroll
        for (int ks = 0; ks < 8; ks++) {
            const int kabs = kt * 64 + ks * 8;
            uint32_t af[4];
            af[0] = __float_as_uint(scores[(warpRowO + lr) * ATT_SC_STRIDE + kabs + lc]);
            af[1] = __float_as_uint(scores[(warpRowO + lr + 8) * ATT_SC_STRIDE + kabs + lc]);
            af[2] = __float_as_uint(scores[(warpRowO + lr) * ATT_SC_STRIDE + kabs + lc + 4]);
            af[3] = __float_as_uint(scores[(warpRowO + lr + 8) * ATT_SC_STRIDE + kabs + lc + 4]);
            #pragma unroll
            for (int jt = 0; jt < 8; jt++) {
                const int ncol = warpColO + jt * 8 + lr;
                uint32_t bf[2];
                bf[0] = __float_as_uint(Vs[(ks * 8 + lc) * 132 + ncol]);
                bf[1] = __float_as_uint(Vs[(ks * 8 + lc + 4) * 132 + ncol]);
                mma_tf32(oacc[jt], af, bf);
            }
        }
        __syncthreads();   // all warps done reading Vs
        if (kt < qt) {
            #pragma unroll
            for (int j = 0; j < 8; j++) {
                int idx = tid + j * 256;
                int r = idx >> 5, c = idx & 31;
                cp16(sKV + r * 528 + c * 16,
                     Vbase + (size_t)((kt + 1) * 64 + r) * KVROW + c * 4);
            }
            cp_commit();
        }
    }

    // write O (tf32-rounded; feeds the Wo GEMM)
    #pragma unroll
    for (int jt = 0; jt < 8; jt++) {
        int r0 = qt * 64 + warpRowO + lr;
        int col = h * HEADD + warpColO + jt * 8 + 2 * lc;
        float* d0 = &O[((size_t)b * SEQ + r0) * DMODEL + col];
        float* d1 = &O[((size_t)b * SEQ + r0 + 8) * DMODEL + col];
        float2 v0 = make_float2(rna_tf32f(oacc[jt][0]), rna_tf32f(oacc[jt][1]));
        float2 v1 = make_float2(rna_tf32f(oacc[jt][2]), rna_tf32f(oacc[jt][3]));
        *reinterpret_cast<float2*>(d0) = v0;
        *reinterpret_cast<float2*>(d1) = v1;
    }
}

// ---------------------------------------------------------------------------
// Launch
// ---------------------------------------------------------------------------
extern "C" void kernel_launch(void* const* d_in, const int* in_sizes, int n_in,
                              void* d_out, int out_size) {
    const float* x  = (const float*)d_in[0];
    const float* Wq = (const float*)d_in[1];
    const float* bq = (const float*)d_in[2];
    const float* Wk = (const float*)d_in[3];
    const float* bk = (const float*)d_in[4];
    const float* Wv = (const float*)d_in[5];
    const float* bv = (const float*)d_in[6];
    const float* Wo = (const float*)d_in[7];
    const float* bo = (const float*)d_in[8];
    const float* qns = (const float*)d_in[9];
    const float* kns = (const float*)d_in[10];
    float* out = (float*)d_out;

    float *qb, *kvb, *ab, *xr, *wqt, *wkvt, *wot, *bkv;
    cudaGetSymbolAddress((void**)&qb, g_q);
    cudaGetSymbolAddress((void**)&kvb, g_kv);
    cudaGetSymbolAddress((void**)&ab, g_attn);
    cudaGetSymbolAddress((void**)&xr, g_xr);
    cudaGetSymbolAddress((void**)&wqt, g_wqt);
    cudaGetSymbolAddress((void**)&wkvt, g_wkvt);
    cudaGetSymbolAddress((void**)&wot, g_wot);
    cudaGetSymbolAddress((void**)&bkv, g_bkv);

    // Pre-pass
    {
        int n4 = MROWS * DMODEL / 4;
        round_x_kernel<<<(n4 + 255) / 256, 256>>>(x, xr, n4);
        dim3 tb(32, 8);
        transpose_round_kernel<<<dim3(DMODEL / 32, DMODEL / 32), tb>>>(Wq, wqt, DMODEL, DMODEL);
        transpose_round_kernel<<<dim3(KVD / 32, DMODEL / 32), tb>>>(Wk, wkvt, DMODEL, KVD);
        transpose_round_kernel<<<dim3(KVD / 32, DMODEL / 32), tb>>>(Wv, wkvt + (size_t)KVD * DMODEL,
                                                                    DMODEL, KVD);
        transpose_round_kernel<<<dim3(DMODEL / 32, DMODEL / 32), tb>>>(Wo, wot, DMODEL, DMODEL);
        concat_bias_kernel<<<4, 256>>>(bk, bv, bkv);
    }

    cudaFuncSetAttribute(tf32_gemm_pipe, cudaFuncAttributeMaxDynamicSharedMemorySize,
                         GEMM_SMEM_BYTES);

    // Q projection (no output rounding; rmsnorm rounds) and fused K|V (rounded)
    tf32_gemm_pipe<<<dim3(DMODEL / 128, MROWS / 128), 256, GEMM_SMEM_BYTES>>>(
        xr, wqt, bq, qb, MROWS, DMODEL, DMODEL, 0);
    tf32_gemm_pipe<<<dim3(KVROW / 128, MROWS / 128), 256, GEMM_SMEM_BYTES>>>(
        xr, wkvt, bkv, kvb, MROWS, KVROW, DMODEL, 1);

    // RMSNorm + RoPE (rounds outputs to tf32)
    rmsnorm_rope_kernel<<<MROWS * NHEADS, 128>>>(qb, qns, NHEADS, DMODEL, INV_SQRT_HD);
    rmsnorm_rope_kernel<<<MROWS * NGROUPS, 128>>>(kvb, kns, NGROUPS, KVROW, 1.0f);

    // Attention (tensor cores)
    cudaFuncSetAttribute(attention_tc_kernel, cudaFuncAttributeMaxDynamicSharedMemorySize,
                         ATT_SMEM_BYTES);
    attention_tc_kernel<<<dim3(SEQ / 64, BATCH * NHEADS), 256, ATT_SMEM_BYTES>>>(qb, kvb, ab);

    // Output projection (final; no rounding)
    tf32_gemm_pipe<<<dim3(DMODEL / 128, MROWS / 128), 256, GEMM_SMEM_BYTES>>>(
        ab, wot, bo, out, MROWS, DMODEL, DMODEL, 0);
}

// round 9
// speedup vs baseline: 4.3363x; 1.0827x over previous
#include <cuda_runtime.h>
#include <cuda_bf16.h>
#include <math.h>
#include <stdint.h>

// Problem constants
#define BATCH 16
#define SEQ   512
#define DMODEL 2048
#define NHEADS 16
#define NGROUPS 4
#define HEADD 128
#define PPG   (NHEADS / NGROUPS)   // 4
#define KVD   (NGROUPS * HEADD)    // 512
#define KVROW 1024                 // fused K|V row width
#define MROWS (BATCH * SEQ)        // 8192

#define INV_SQRT_HD 0.08838834764831845f
#define LN10000 9.210340371976184f

// ---------------------------------------------------------------------------
// Scratch buffers (static __device__, allocation-free)
// ---------------------------------------------------------------------------
__device__ float g_q[(size_t)MROWS * DMODEL];      // 64 MB
__device__ float g_kv[(size_t)MROWS * KVROW];      // 32 MB  (K | V per row)
__device__ float g_attn[(size_t)MROWS * DMODEL];   // 64 MB (tf32-rounded)
__device__ float g_xr[(size_t)MROWS * DMODEL];     // 64 MB (tf32-rounded x)
__device__ float g_wqt[(size_t)DMODEL * DMODEL];   // 16 MB  WqT [N,K]
__device__ float g_wkvt[(size_t)KVROW * DMODEL];   // 8 MB   [WkT ; WvT]
__device__ float g_wot[(size_t)DMODEL * DMODEL];   // 16 MB
__device__ float g_bkv[KVROW];
__device__ float g_sintab[SEQ * 64];
__device__ float g_costab[SEQ * 64];

// ---------------------------------------------------------------------------
// helpers
// ---------------------------------------------------------------------------
__device__ __forceinline__ unsigned f2tf32(float x) {
    unsigned r;
    asm("cvt.rna.tf32.f32 %0, %1;" : "=r"(r) : "f"(x));
    return r;
}
__device__ __forceinline__ float rna_tf32f(float x) { return __uint_as_float(f2tf32(x)); }

__device__ __forceinline__ uint32_t smem_u32(const void* p) {
    uint32_t a;
    asm("{ .reg .u64 t; cvta.to.shared.u64 t, %1; cvt.u32.u64 %0, t; }" : "=r"(a) : "l"(p));
    return a;
}
__device__ __forceinline__ void cp16(uint32_t saddr, const void* g) {
    asm volatile("cp.async.cg.shared.global [%0], [%1], 16;" :: "r"(saddr), "l"(g));
}
__device__ __forceinline__ void cp_commit() { asm volatile("cp.async.commit_group;" ::: "memory"); }

__device__ __forceinline__ void ldsm_x4(uint32_t a[4], uint32_t addr) {
    asm volatile("ldmatrix.sync.aligned.m8n8.x4.shared.b16 {%0,%1,%2,%3}, [%4];"
                 : "=r"(a[0]), "=r"(a[1]), "=r"(a[2]), "=r"(a[3]) : "r"(addr));
}
__device__ __forceinline__ void ldsm_x2(uint32_t a[2], uint32_t addr) {
    asm volatile("ldmatrix.sync.aligned.m8n8.x2.shared.b16 {%0,%1}, [%2];"
                 : "=r"(a[0]), "=r"(a[1]) : "r"(addr));
}

__device__ __forceinline__ void mma_tf32(float c[4], const uint32_t a[4], const uint32_t b[2]) {
    asm volatile(
        "mma.sync.aligned.m16n8k8.row.col.f32.tf32.tf32.f32 "
        "{%0,%1,%2,%3}, {%4,%5,%6,%7}, {%8,%9}, {%0,%1,%2,%3};"
        : "+f"(c[0]), "+f"(c[1]), "+f"(c[2]), "+f"(c[3])
        : "r"(a[0]), "r"(a[1]), "r"(a[2]), "r"(a[3]), "r"(b[0]), "r"(b[1]));
}

// ---------------------------------------------------------------------------
// Pre-pass kernels
// ---------------------------------------------------------------------------
__global__ void rope_table_kernel(float* __restrict__ sintab, float* __restrict__ costab) {
    const int s = blockIdx.x;
    const int i = threadIdx.x;   // 0..63
    float inv_freq = expf((float)i * (-LN10000 / 64.0f));
    float sn, cs;
    sincosf((float)s * inv_freq, &sn, &cs);
    sintab[s * 64 + i] = sn;
    costab[s * 64 + i] = cs;
}

__global__ void round_x_kernel(const float* __restrict__ x, float* __restrict__ xr, int n4) {
    int i = blockIdx.x * blockDim.x + threadIdx.x;
    if (i < n4) {
        float4 v = reinterpret_cast<const float4*>(x)[i];
        v.x = rna_tf32f(v.x); v.y = rna_tf32f(v.y);
        v.z = rna_tf32f(v.z); v.w = rna_tf32f(v.w);
        reinterpret_cast<float4*>(xr)[i] = v;
    }
}

// WT[n][k] = round(W[k][n]);  W is [K,N]
__global__ void transpose_round_kernel(const float* __restrict__ W, float* __restrict__ WT,
                                       int K, int N) {
    __shared__ float t[32][33];
    int n0 = blockIdx.x * 32, k0 = blockIdx.y * 32;
    int tx = threadIdx.x, ty = threadIdx.y;
    #pragma unroll
    for (int j = 0; j < 32; j += 8)
        t[ty + j][tx] = W[(size_t)(k0 + ty + j) * N + n0 + tx];
    __syncthreads();
    #pragma unroll
    for (int j = 0; j < 32; j += 8)
        WT[(size_t)(n0 + ty + j) * K + k0 + tx] = rna_tf32f(t[tx][ty + j]);
}

__global__ void concat_bias_kernel(const float* __restrict__ bk, const float* __restrict__ bv,
                                   float* __restrict__ bkv) {
    int i = blockIdx.x * blockDim.x + threadIdx.x;
    if (i < KVROW) bkv[i] = (i < KVD) ? bk[i] : bv[i - KVD];
}

// ---------------------------------------------------------------------------
// TF32 mma.sync GEMM: C[M,N] = A[M,K] @ BT[N,K]^T + bias[N]
// CTA 128x128, BK=32, 3-stage cp.async, ldmatrix fragments.
// ---------------------------------------------------------------------------
#define BK 32
#define STAGE_BYTES 32768          // A 16KB + B 16KB
#define GSM_B_OFF 16384
#define GEMM_SMEM_BYTES (3 * STAGE_BYTES)   // 98304

__device__ __forceinline__ uint32_t swz(int r, int chunk) {
    return (uint32_t)(r * 128 + ((chunk ^ (r & 7)) << 4));
}

__device__ __forceinline__ void gemm_load_stage(const float* __restrict__ A,
                                                const float* __restrict__ BT,
                                                int K, int m0, int n0, int kt,
                                                uint32_t sstage, int tid) {
    const int kbase = kt * BK;
    #pragma unroll
    for (int j = 0; j < 4; j++) {
        int i = tid + j * 256;
        int r = i >> 3, cc = i & 7;
        cp16(sstage + swz(r, cc), A + (size_t)(m0 + r) * K + kbase + cc * 4);
    }
    #pragma unroll
    for (int j = 0; j < 4; j++) {
        int i = tid + j * 256;
        int r = i >> 3, cc = i & 7;
        cp16(sstage + GSM_B_OFF + swz(r, cc), BT + (size_t)(n0 + r) * K + kbase + cc * 4);
    }
}

__global__ __launch_bounds__(256, 2)
void tf32_gemm_pipe(const float* __restrict__ A, const float* __restrict__ BT,
                    const float* __restrict__ bias, float* __restrict__ C,
                    int M, int N, int K, int roundC) {
    extern __shared__ char smem[];
    const uint32_t sbase = smem_u32(smem);
    const int tid = threadIdx.x;
    const int lane = tid & 31;
    const int wid = tid >> 5;
    const int warpRow = (wid >> 2) * 64;
    const int warpCol = (wid & 3) * 32;
    const int m0 = blockIdx.y * 128;
    const int n0 = blockIdx.x * 128;

    float acc[4][4][4];
    #pragma unroll
    for (int i = 0; i < 4; i++)
        #pragma unroll
        for (int j = 0; j < 4; j++)
            #pragma unroll
            for (int r = 0; r < 4; r++) acc[i][j][r] = 0.0f;

    const int NT = K / BK;

    const int a_sub = lane >> 3;
    const int a_row_in = (lane & 7) + (a_sub & 1) * 8;
    const int a_chunk_add = a_sub >> 1;
    const int b_sub = (lane >> 3) & 1;
    const int b_row_in = lane & 7;

    gemm_load_stage(A, BT, K, m0, n0, 0, sbase, tid);
    cp_commit();
    gemm_load_stage(A, BT, K, m0, n0, 1, sbase + STAGE_BYTES, tid);
    cp_commit();

    for (int kt = 0; kt < NT; kt++) {
        if (kt + 2 < NT) {
            asm volatile("cp.async.wait_group 1;" ::: "memory");
        } else {
            asm volatile("cp.async.wait_group 0;" ::: "memory");
        }
        __syncthreads();
        if (kt + 2 < NT) {
            gemm_load_stage(A, BT, K, m0, n0, kt + 2,
                            sbase + ((kt + 2) % 3) * STAGE_BYTES, tid);
            cp_commit();
        }

        const uint32_t sA = sbase + (kt % 3) * STAGE_BYTES;
        const uint32_t sB = sA + GSM_B_OFF;

        #pragma unroll
        for (int ks = 0; ks < 4; ks++) {
            uint32_t af[4][4];
            uint32_t bf[4][2];
            #pragma unroll
            for (int it = 0; it < 4; it++) {
                int r = warpRow + it * 16 + a_row_in;
                int chunk = ks * 2 + a_chunk_add;
                ldsm_x4(af[it], sA + swz(r, chunk));
            }
            #pragma unroll
            for (int jt = 0; jt < 4; jt++) {
                int r = warpCol + jt * 8 + b_row_in;
                int chunk = ks * 2 + b_sub;
                ldsm_x2(bf[jt], sB + swz(r, chunk));
            }
            #pragma unroll
            for (int it = 0; it < 4; it++)
                #pragma unroll
                for (int jt = 0; jt < 4; jt++)
                    mma_tf32(acc[it][jt], af[it], bf[jt]);
        }
    }

    const int lr = lane >> 2;
    const int lc = lane & 3;
    #pragma unroll
    for (int it = 0; it < 4; it++) {
        #pragma unroll
        for (int jt = 0; jt < 4; jt++) {
            int row = m0 + warpRow + it * 16 + lr;
            int col = n0 + warpCol + jt * 8 + 2 * lc;
            float b0 = bias[col];
            float b1 = bias[col + 1];
            float2 v0 = make_float2(acc[it][jt][0] + b0, acc[it][jt][1] + b1);
            float2 v1 = make_float2(acc[it][jt][2] + b0, acc[it][jt][3] + b1);
            if (roundC) {
                v0.x = rna_tf32f(v0.x); v0.y = rna_tf32f(v0.y);
                v1.x = rna_tf32f(v1.x); v1.y = rna_tf32f(v1.y);
            }
            *reinterpret_cast<float2*>(&C[(size_t)row * N + col]) = v0;
            *reinterpret_cast<float2*>(&C[(size_t)(row + 8) * N + col]) = v1;
        }
    }
}

// ---------------------------------------------------------------------------
// fast fused RMSNorm + RoPE: one warp per 128-vector, table-based trig,
// float4 traffic, shuffle-only reduction. Output tf32-rounded.
// grid = nvec/8 blocks of 256 threads.
// ---------------------------------------------------------------------------
__global__ __launch_bounds__(256)
void rmsnorm_rope_fast(float* __restrict__ buf, const float* __restrict__ scale,
                       const float* __restrict__ sintab, const float* __restrict__ costab,
                       int heads_per_row, int rowstride, float post_scale) {
    const int vec = blockIdx.x * 8 + (threadIdx.x >> 5);
    const int lane = threadIdx.x & 31;
    const int row = vec / heads_per_row;
    const int head = vec % heads_per_row;
    float* ptr = buf + (size_t)row * rowstride + head * HEADD + lane * 4;
    const int s = row & (SEQ - 1);

    float4 v = *reinterpret_cast<const float4*>(ptr);
    float sq = fmaf(v.x, v.x, fmaf(v.y, v.y, fmaf(v.z, v.z, v.w * v.w)));
    #pragma unroll
    for (int o = 16; o > 0; o >>= 1) sq += __shfl_xor_sync(0xffffffffu, sq, o);
    const float r = rsqrtf(sq * (1.0f / 128.0f) + 1e-6f);

    const float4 sc = *reinterpret_cast<const float4*>(scale + lane * 4);
    const float a0 = v.x * r * sc.x;
    const float a1 = v.y * r * sc.y;
    const float a2 = v.z * r * sc.z;
    const float a3 = v.w * r * sc.w;

    const float2 sn = *reinterpret_cast<const float2*>(sintab + s * 64 + lane * 2);
    const float2 cs = *reinterpret_cast<const float2*>(costab + s * 64 + lane * 2);

    float4 o4;
    o4.x = rna_tf32f(fmaf(a0, cs.x, -a1 * sn.x) * post_scale);
    o4.y = rna_tf32f(fmaf(a0, sn.x,  a1 * cs.x) * post_scale);
    o4.z = rna_tf32f(fmaf(a2, cs.y, -a3 * sn.y) * post_scale);
    o4.w = rna_tf32f(fmaf(a2, sn.y,  a3 * cs.y) * post_scale);
    *reinterpret_cast<float4*>(ptr) = o4;
}

// ---------------------------------------------------------------------------
// Tensor-core causal attention (unchanged from R6)
// ---------------------------------------------------------------------------
#define ATT_SC_STRIDE 516
#define ATT_Q_OFF  (64 * ATT_SC_STRIDE * 4)            // 132096
#define ATT_KV_OFF (ATT_Q_OFF + 32768)                 // 164864
#define ATT_SMEM_BYTES (ATT_KV_OFF + 65536)            // 230400

__device__ __forceinline__ uint32_t qswz(int r, int c) {
    return (uint32_t)(r * 512 + ((((c ^ r) & 7) | (c & 24)) << 4));
}

__global__ __launch_bounds__(256, 1)
void attention_tc_kernel(const float* __restrict__ Q, const float* __restrict__ KV,
                         float* __restrict__ O) {
    extern __shared__ char smemraw[];
    float* scores = reinterpret_cast<float*>(smemraw);
    float* Vs = reinterpret_cast<float*>(smemraw + ATT_KV_OFF);
    const uint32_t sbase = smem_u32(smemraw);
    const uint32_t sQ = sbase + ATT_Q_OFF;
    const uint32_t sKV = sbase + ATT_KV_OFF;

    const int tid = threadIdx.x;
    const int lane = tid & 31;
    const int wid = tid >> 5;
    const int qt = blockIdx.x;
    const int bh = blockIdx.y;
    const int b = bh / NHEADS;
    const int h = bh % NHEADS;
    const int g = h / PPG;

    const float* Qbase = Q + (size_t)b * SEQ * DMODEL + (size_t)h * HEADD;
    const float* Kbase = KV + (size_t)b * SEQ * KVROW + (size_t)g * HEADD;
    const float* Vbase = KV + (size_t)b * SEQ * KVROW + KVD + (size_t)g * HEADD;

    #pragma unroll
    for (int j = 0; j < 8; j++) {
        int idx = tid + j * 256;
        int r = idx >> 5, c = idx & 31;
        cp16(sQ + qswz(r, c), Qbase + (size_t)(qt * 64 + r) * DMODEL + c * 4);
    }
    #pragma unroll
    for (int j = 0; j < 8; j++) {
        int idx = tid + j * 256;
        int r = idx >> 5, c = idx & 31;
        cp16(sKV + qswz(r, c), Kbase + (size_t)r * KVROW + c * 4);
    }
    cp_commit();
    asm volatile("cp.async.wait_group 0;" ::: "memory");
    __syncthreads();

    const int a_sub = lane >> 3;
    const int a_row_in = (lane & 7) + (a_sub & 1) * 8;
    const int a_chunk_add = a_sub >> 1;
    const int b_row_in = lane & 7;
    const int b_sub = (lane >> 3) & 1;
    const int lr = lane >> 2;
    const int lc = lane & 3;
    const int warpRowS = (wid & 3) * 16;
    const int warpColS = (wid >> 2) * 32;

    // ---------------- phase 1: scores = Q @ K^T ----------------
    for (int kt = 0; kt <= qt; kt++) {
        const int buf = kt & 1;
        if (kt < qt) {
            #pragma unroll
            for (int j = 0; j < 8; j++) {
                int idx = tid + j * 256;
                int r = idx >> 5, c = idx & 31;
                cp16(sKV + (1 - buf) * 32768 + qswz(r, c),
                     Kbase + (size_t)((kt + 1) * 64 + r) * KVROW + c * 4);
            }
            cp_commit();
        }
        const uint32_t sK = sKV + buf * 32768;

        float acc[4][4];
        #pragma unroll
        for (int i = 0; i < 4; i++)
            #pragma unroll
            for (int j = 0; j < 4; j++) acc[i][j] = 0.0f;

        #pragma unroll
        for (int ks = 0; ks < 16; ks++) {
            uint32_t af[4];
            ldsm_x4(af, sQ + qswz(warpRowS + a_row_in, ks * 2 + a_chunk_add));
            #pragma unroll
            for (int jt = 0; jt < 4; jt++) {
                uint32_t bf[2];
                ldsm_x2(bf, sK + qswz(warpColS + jt * 8 + b_row_in, ks * 2 + b_sub));
                mma_tf32(acc[jt], af, bf);
            }
        }

        #pragma unroll
        for (int jt = 0; jt < 4; jt++) {
            int r0 = warpRowS + lr;
            int r1 = r0 + 8;
            int c0 = kt * 64 + warpColS + jt * 8 + 2 * lc;
            int g0 = qt * 64 + r0;
            int g1 = qt * 64 + r1;
            float2 v0, v1;
            v0.x = (c0 <= g0) ? acc[jt][0] * INV_SQRT_HD : -1e30f;
            v0.y = (c0 + 1 <= g0) ? acc[jt][1] * INV_SQRT_HD : -1e30f;
            v1.x = (c0 <= g1) ? acc[jt][2] * INV_SQRT_HD : -1e30f;
            v1.y = (c0 + 1 <= g1) ? acc[jt][3] * INV_SQRT_HD : -1e30f;
            *reinterpret_cast<float2*>(&scores[r0 * ATT_SC_STRIDE + c0]) = v0;
            *reinterpret_cast<float2*>(&scores[r1 * ATT_SC_STRIDE + c0]) = v1;
        }
        if (kt < qt) asm volatile("cp.async.wait_group 0;" ::: "memory");
        __syncthreads();
    }

    // prefetch V tile 0
    #pragma unroll
    for (int j = 0; j < 8; j++) {
        int idx = tid + j * 256;
        int r = idx >> 5, c = idx & 31;
        cp16(sKV + r * 528 + c * 16, Vbase + (size_t)r * KVROW + c * 4);
    }
    cp_commit();

    // ---------------- phase 2: softmax ----------------
    {
        const int ncols = (qt + 1) * 64;
        for (int r = wid; r < 64; r += 8) {
            float* row = &scores[r * ATT_SC_STRIDE];
            float m = -1e30f;
            for (int c = lane; c < ncols; c += 32) m = fmaxf(m, row[c]);
            #pragma unroll
            for (int o = 16; o > 0; o >>= 1) m = fmaxf(m, __shfl_xor_sync(0xffffffffu, m, o));
            float sum = 0.0f;
            for (int c = lane; c < ncols; c += 32) {
                float e = __expf(row[c] - m);
                row[c] = e;
                sum += e;
            }
            #pragma unroll
            for (int o = 16; o > 0; o >>= 1) sum += __shfl_xor_sync(0xffffffffu, sum, o);
            float inv = 1.0f / sum;
            for (int c = lane; c < ncols; c += 32) row[c] = rna_tf32f(row[c] * inv);
        }
    }
    __syncthreads();

    // ---------------- phase 3: O = P @ V ----------------
    const int warpRowO = (wid & 3) * 16;
    const int warpColO = (wid >> 2) * 64;
    float oacc[8][4];
    #pragma unroll
    for (int i = 0; i < 8; i++)
        #pragma unroll
        for (int j = 0; j < 4; j++) oacc[i][j] = 0.0f;

    for (int kt = 0; kt <= qt; kt++) {
        asm volatile("cp.async.wait_group 0;" ::: "memory");
        __syncthreads();

        #pragma unroll
        for (int ks = 0; ks < 8; ks++) {
            const int kabs = kt * 64 + ks * 8;
            uint32_t af[4];
            af[0] = __float_as_uint(scores[(warpRowO + lr) * ATT_SC_STRIDE + kabs + lc]);
            af[1] = __float_as_uint(scores[(warpRowO + lr + 8) * ATT_SC_STRIDE + kabs + lc]);
            af[2] = __float_as_uint(scores[(warpRowO + lr) * ATT_SC_STRIDE + kabs + lc + 4]);
            af[3] = __float_as_uint(scores[(warpRowO + lr + 8) * ATT_SC_STRIDE + kabs + lc + 4]);
            #pragma unroll
            for (int jt = 0; jt < 8; jt++) {
                const int ncol = warpColO + jt * 8 + lr;
                uint32_t bf[2];
                bf[0] = __float_as_uint(Vs[(ks * 8 + lc) * 132 + ncol]);
                bf[1] = __float_as_uint(Vs[(ks * 8 + lc + 4) * 132 + ncol]);
                mma_tf32(oacc[jt], af, bf);
            }
        }
        __syncthreads();
        if (kt < qt) {
            #pragma unroll
            for (int j = 0; j < 8; j++) {
                int idx = tid + j * 256;
                int r = idx >> 5, c = idx & 31;
                cp16(sKV + r * 528 + c * 16,
                     Vbase + (size_t)((kt + 1) * 64 + r) * KVROW + c * 4);
            }
            cp_commit();
        }
    }

    #pragma unroll
    for (int jt = 0; jt < 8; jt++) {
        int r0 = qt * 64 + warpRowO + lr;
        int col = h * HEADD + warpColO + jt * 8 + 2 * lc;
        float* d0 = &O[((size_t)b * SEQ + r0) * DMODEL + col];
        float* d1 = &O[((size_t)b * SEQ + r0 + 8) * DMODEL + col];
        float2 v0 = make_float2(rna_tf32f(oacc[jt][0]), rna_tf32f(oacc[jt][1]));
        float2 v1 = make_float2(rna_tf32f(oacc[jt][2]), rna_tf32f(oacc[jt][3]));
        *reinterpret_cast<float2*>(d0) = v0;
        *reinterpret_cast<float2*>(d1) = v1;
    }
}

// ---------------------------------------------------------------------------
// Launch: two-branch graph (default stream + side stream joined by events)
// ---------------------------------------------------------------------------
extern "C" void kernel_launch(void* const* d_in, const int* in_sizes, int n_in,
                              void* d_out, int out_size) {
    const float* x  = (const float*)d_in[0];
    const float* Wq = (const float*)d_in[1];
    const float* bq = (const float*)d_in[2];
    const float* Wk = (const float*)d_in[3];
    const float* bk = (const float*)d_in[4];
    const float* Wv = (const float*)d_in[5];
    const float* bv = (const float*)d_in[6];
    const float* Wo = (const float*)d_in[7];
    const float* bo = (const float*)d_in[8];
    const float* qns = (const float*)d_in[9];
    const float* kns = (const float*)d_in[10];
    float* out = (float*)d_out;

    float *qb, *kvb, *ab, *xr, *wqt, *wkvt, *wot, *bkv, *stab, *ctab;
    cudaGetSymbolAddress((void**)&qb, g_q);
    cudaGetSymbolAddress((void**)&kvb, g_kv);
    cudaGetSymbolAddress((void**)&ab, g_attn);
    cudaGetSymbolAddress((void**)&xr, g_xr);
    cudaGetSymbolAddress((void**)&wqt, g_wqt);
    cudaGetSymbolAddress((void**)&wkvt, g_wkvt);
    cudaGetSymbolAddress((void**)&wot, g_wot);
    cudaGetSymbolAddress((void**)&bkv, g_bkv);
    cudaGetSymbolAddress((void**)&stab, g_sintab);
    cudaGetSymbolAddress((void**)&ctab, g_costab);

    cudaFuncSetAttribute(tf32_gemm_pipe, cudaFuncAttributeMaxDynamicSharedMemorySize,
                         GEMM_SMEM_BYTES);
    cudaFuncSetAttribute(attention_tc_kernel, cudaFuncAttributeMaxDynamicSharedMemorySize,
                         ATT_SMEM_BYTES);

    cudaStream_t skv;
    cudaEvent_t ev_root, ev_x, ev_kv;
    cudaStreamCreateWithFlags(&skv, cudaStreamNonBlocking);
    cudaEventCreateWithFlags(&ev_root, cudaEventDisableTiming);
    cudaEventCreateWithFlags(&ev_x, cudaEventDisableTiming);
    cudaEventCreateWithFlags(&ev_kv, cudaEventDisableTiming);

    dim3 tb(32, 8);

    // fork point
    cudaEventRecord(ev_root, 0);
    cudaStreamWaitEvent(skv, ev_root, 0);

    // default-stream branch: tables, x rounding, Wq/Wo transpose, Q path
    rope_table_kernel<<<SEQ, 64>>>(stab, ctab);
    {
        int n4 = MROWS * DMODEL / 4;
        round_x_kernel<<<(n4 + 255) / 256, 256>>>(x, xr, n4);
    }
    cudaEventRecord(ev_x, 0);    // xr + tables ready

    transpose_round_kernel<<<dim3(DMODEL / 32, DMODEL / 32), tb>>>(Wq, wqt, DMODEL, DMODEL);
    transpose_round_kernel<<<dim3(DMODEL / 32, DMODEL / 32), tb>>>(Wo, wot, DMODEL, DMODEL);
    tf32_gemm_pipe<<<dim3(DMODEL / 128, MROWS / 128), 256, GEMM_SMEM_BYTES>>>(
        xr, wqt, bq, qb, MROWS, DMODEL, DMODEL, 0);
    rmsnorm_rope_fast<<<MROWS * NHEADS / 8, 256>>>(qb, qns, stab, ctab,
                                                   NHEADS, DMODEL, INV_SQRT_HD);

    // side-stream branch: Wk/Wv transpose, KV GEMM, K rmsnorm
    transpose_round_kernel<<<dim3(KVD / 32, DMODEL / 32), tb, 0, skv>>>(Wk, wkvt, DMODEL, KVD);
    transpose_round_kernel<<<dim3(KVD / 32, DMODEL / 32), tb, 0, skv>>>(
        Wv, wkvt + (size_t)KVD * DMODEL, DMODEL, KVD);
    concat_bias_kernel<<<4, 256, 0, skv>>>(bk, bv, bkv);
    cudaStreamWaitEvent(skv, ev_x, 0);
    tf32_gemm_pipe<<<dim3(KVROW / 128, MROWS / 128), 256, GEMM_SMEM_BYTES, skv>>>(
        xr, wkvt, bkv, kvb, MROWS, KVROW, DMODEL, 1);
    rmsnorm_rope_fast<<<MROWS * NGROUPS / 8, 256, 0, skv>>>(kvb, kns, stab, ctab,
                                                            NGROUPS, KVROW, 1.0f);
    cudaEventRecord(ev_kv, skv);

    // join, then attention + output projection on default stream
    cudaStreamWaitEvent(0, ev_kv, 0);
    attention_tc_kernel<<<dim3(SEQ / 64, BATCH * NHEADS), 256, ATT_SMEM_BYTES>>>(qb, kvb, ab);
    tf32_gemm_pipe<<<dim3(DMODEL / 128, MROWS / 128), 256, GEMM_SMEM_BYTES>>>(
        ab, wot, bo, out, MROWS, DMODEL, DMODEL, 0);
}